// round 1
// baseline (speedup 1.0000x reference)
#include <cuda_runtime.h>

// Problem constants
#define BATCH 16
#define CIN   256
#define MED   128
#define NPIX  4096   // 64*64

// ---------------- scratch (static __device__, no allocations) ----------------
__device__ float g_W[256 * 256];              // stacked [w_o; w_v], row-major [256][256]
__device__ float g_bias[256];                 // stacked [b_o; b_v]
__device__ float g_ov[BATCH * 256 * NPIX];    // rows 0..127 = o, 128..255 = v
__device__ float g_xv[BATCH * MED * NPIX];    // softmax over N of v
__device__ float g_xs[BATCH * MED * NPIX];    // softmax over M of v (stored [b][m][n])
__device__ float g_Apart[BATCH * 16 * MED * MED]; // split-K partials of A
__device__ float g_A[BATCH * MED * MED];      // A[b][m][k]
__device__ float g_Wb[BATCH * 256 * MED];     // Wb[b][c][m] = sum_k w_c[c][k] A[b][m][k]

// ---------------- prep: stack weights/bias ----------------
__global__ void k_prep(const float* __restrict__ w_o, const float* __restrict__ b_o,
                       const float* __restrict__ w_v, const float* __restrict__ b_v) {
    int i = blockIdx.x * blockDim.x + threadIdx.x;   // 0..32767
    if (i < 128 * 256) {
        g_W[i] = w_o[i];
        g_W[128 * 256 + i] = w_v[i];
    }
    if (i < 128) {
        g_bias[i] = b_o[i];
        g_bias[128 + i] = b_v[i];
    }
}

// ---------------- K1: ov = W_stack @ x + bias ----------------
// grid (NPIX/128, 256/128, B), block 256. Tile 128x128, K-tile 16, 8x8 microtile.
__global__ __launch_bounds__(256, 2)
void k_gemm_ov(const float* __restrict__ x) {
    __shared__ float As[16][132];   // As[k][m]
    __shared__ float Bs[16][132];   // Bs[k][n]
    const int b    = blockIdx.z;
    const int row0 = blockIdx.y * 128;
    const int col0 = blockIdx.x * 128;
    const float* X = x + (size_t)b * CIN * NPIX;
    const int t  = threadIdx.x;
    const int tm = t >> 4, tn = t & 15;

    float acc[8][8];
#pragma unroll
    for (int i = 0; i < 8; i++)
#pragma unroll
        for (int j = 0; j < 8; j++) acc[i][j] = 0.f;

    for (int kk = 0; kk < 256; kk += 16) {
        // A tile: 128 m x 16 k (float4 along k)
#pragma unroll
        for (int i = 0; i < 2; i++) {
            int lin = t * 2 + i;            // 0..511
            int m = lin >> 2, kq = lin & 3;
            float4 v4 = *(const float4*)(g_W + (size_t)(row0 + m) * 256 + kk + kq * 4);
            As[kq * 4 + 0][m] = v4.x;
            As[kq * 4 + 1][m] = v4.y;
            As[kq * 4 + 2][m] = v4.z;
            As[kq * 4 + 3][m] = v4.w;
        }
        // B tile: 16 k x 128 n (float4 along n)
#pragma unroll
        for (int i = 0; i < 2; i++) {
            int lin = t + i * 256;          // 0..511
            int k = lin >> 5, nq = lin & 31;
            float4 v4 = *(const float4*)(X + (size_t)(kk + k) * NPIX + col0 + nq * 4);
            *(float4*)&Bs[k][nq * 4] = v4;
        }
        __syncthreads();
#pragma unroll
        for (int k = 0; k < 16; k++) {
            float a[8], bb[8];
#pragma unroll
            for (int i = 0; i < 8; i++) a[i] = As[k][tm * 8 + i];
#pragma unroll
            for (int j = 0; j < 8; j++) bb[j] = Bs[k][tn * 8 + j];
#pragma unroll
            for (int i = 0; i < 8; i++)
#pragma unroll
                for (int j = 0; j < 8; j++) acc[i][j] += a[i] * bb[j];
        }
        __syncthreads();
    }

    float* out = g_ov + (size_t)b * 256 * NPIX;
#pragma unroll
    for (int i = 0; i < 8; i++) {
        int r = row0 + tm * 8 + i;
        float bias = g_bias[r];
        float4 o0, o1;
        o0.x = acc[i][0] + bias; o0.y = acc[i][1] + bias;
        o0.z = acc[i][2] + bias; o0.w = acc[i][3] + bias;
        o1.x = acc[i][4] + bias; o1.y = acc[i][5] + bias;
        o1.z = acc[i][6] + bias; o1.w = acc[i][7] + bias;
        float* p = out + (size_t)r * NPIX + col0 + tn * 8;
        *(float4*)p = o0;
        *(float4*)(p + 4) = o1;
    }
}

// ---------------- K2: row softmax of v (over N=4096) -> g_xv ----------------
// grid B*128 blocks, 256 threads
__global__ void k_softmax_rows() {
    const int bm = blockIdx.x;           // 0..2047
    const int b = bm >> 7, m = bm & 127;
    const float* row = g_ov + (size_t)b * 256 * NPIX + (size_t)(128 + m) * NPIX;
    float* out = g_xv + (size_t)bm * NPIX;

    __shared__ float buf[4096];
    __shared__ float red[9];
    const int t = threadIdx.x;

    float lmax = -1e30f;
    for (int i = t; i < 4096; i += 256) {
        float v = row[i];
        buf[i] = v;
        lmax = fmaxf(lmax, v);
    }
#pragma unroll
    for (int o = 16; o; o >>= 1) lmax = fmaxf(lmax, __shfl_xor_sync(~0u, lmax, o));
    if ((t & 31) == 0) red[t >> 5] = lmax;
    __syncthreads();
    float mx = fmaxf(fmaxf(fmaxf(red[0], red[1]), fmaxf(red[2], red[3])),
                     fmaxf(fmaxf(red[4], red[5]), fmaxf(red[6], red[7])));
    __syncthreads();

    float lsum = 0.f;
    for (int i = t; i < 4096; i += 256) {
        float e = __expf(buf[i] - mx);
        buf[i] = e;
        lsum += e;
    }
#pragma unroll
    for (int o = 16; o; o >>= 1) lsum += __shfl_xor_sync(~0u, lsum, o);
    if ((t & 31) == 0) red[t >> 5] = lsum;
    __syncthreads();
    float inv = 1.f / (red[0] + red[1] + red[2] + red[3] + red[4] + red[5] + red[6] + red[7]);

    for (int i = t; i < 4096; i += 256) out[i] = buf[i] * inv;
}

// ---------------- K3: col softmax of v (over M=128) -> g_xs ----------------
// grid B*N/256 blocks, 256 threads; one pixel per thread
__global__ void k_softmax_cols() {
    const int idx = blockIdx.x * blockDim.x + threadIdx.x; // 0..65535
    const int b = idx >> 12, n = idx & 4095;
    const float* base = g_ov + (size_t)b * 256 * NPIX + (size_t)128 * NPIX + n;

    float mx = -1e30f;
#pragma unroll 4
    for (int m = 0; m < 128; m++) mx = fmaxf(mx, base[(size_t)m * NPIX]);
    float s = 0.f;
#pragma unroll 4
    for (int m = 0; m < 128; m++) s += __expf(base[(size_t)m * NPIX] - mx);
    float inv = 1.f / s;
    float* out = g_xs + (size_t)b * MED * NPIX + n;
#pragma unroll 4
    for (int m = 0; m < 128; m++)
        out[(size_t)m * NPIX] = __expf(base[(size_t)m * NPIX] - mx) * inv;
}

// ---------------- K4: A partials: A[b] = x_v @ x_s^T, split-K over N ----------------
// grid (16 splits, B), block 256, each block covers 256 n's
__global__ __launch_bounds__(256, 2)
void k_gemmA_part() {
    __shared__ float XV[16][132];  // XV[nt][m]
    __shared__ float XS[16][132];  // XS[nt][k]
    const int split = blockIdx.x;
    const int b = blockIdx.y;
    const int n0 = split * 256;
    const float* xv = g_xv + (size_t)b * MED * NPIX;
    const float* xs = g_xs + (size_t)b * MED * NPIX;
    const int t = threadIdx.x;
    const int tm = t >> 4, tn = t & 15;

    float acc[8][8];
#pragma unroll
    for (int i = 0; i < 8; i++)
#pragma unroll
        for (int j = 0; j < 8; j++) acc[i][j] = 0.f;

    for (int nn = 0; nn < 256; nn += 16) {
#pragma unroll
        for (int i = 0; i < 8; i++) {
            int lin = t + i * 256;            // 0..2047 = m*16 + nt
            int m = lin >> 4, nt = lin & 15;
            XV[nt][m] = xv[(size_t)m * NPIX + n0 + nn + nt];
            XS[nt][m] = xs[(size_t)m * NPIX + n0 + nn + nt];
        }
        __syncthreads();
#pragma unroll
        for (int k = 0; k < 16; k++) {
            float a[8], s[8];
#pragma unroll
            for (int i = 0; i < 8; i++) a[i] = XV[k][tm * 8 + i];
#pragma unroll
            for (int j = 0; j < 8; j++) s[j] = XS[k][tn * 8 + j];
#pragma unroll
            for (int i = 0; i < 8; i++)
#pragma unroll
                for (int j = 0; j < 8; j++) acc[i][j] += a[i] * s[j];
        }
        __syncthreads();
    }

    float* out = g_Apart + ((size_t)b * 16 + split) * (MED * MED);
#pragma unroll
    for (int i = 0; i < 8; i++)
#pragma unroll
        for (int j = 0; j < 8; j++)
            out[(size_t)(tm * 8 + i) * MED + tn * 8 + j] = acc[i][j];
}

// ---------------- K4b: reduce partials -> g_A ----------------
__global__ void k_reduceA() {
    const int b = blockIdx.x;
    for (int idx = threadIdx.x; idx < MED * MED; idx += 256) {
        float s = 0.f;
#pragma unroll
        for (int p = 0; p < 16; p++)
            s += g_Apart[((size_t)b * 16 + p) * (MED * MED) + idx];
        g_A[(size_t)b * MED * MED + idx] = s;
    }
}

// ---------------- K5: Wb[b][c][m] = sum_k w_c[c][k] * A[b][m][k] ----------------
// grid (B, 2 c-halves), block 256; thread computes 8c x 8m
__global__ __launch_bounds__(256, 2)
void k_gemmWb(const float* __restrict__ w_c) {
    __shared__ float As[32][136];  // As[k][m]
    __shared__ float Ws[128][33];  // Ws[c_local][k]
    const int b = blockIdx.x;
    const int ch = blockIdx.y;     // c half
    const float* Ab = g_A + (size_t)b * MED * MED;
    const int t = threadIdx.x;
    const int tc = t >> 4, tmn = t & 15;

    float acc[8][8];
#pragma unroll
    for (int i = 0; i < 8; i++)
#pragma unroll
        for (int j = 0; j < 8; j++) acc[i][j] = 0.f;

    for (int k0 = 0; k0 < 128; k0 += 32) {
#pragma unroll
        for (int i = 0; i < 16; i++) {
            int lin = t + i * 256;           // m*32 + kk
            int m = lin >> 5, kk = lin & 31;
            As[kk][m] = Ab[(size_t)m * 128 + k0 + kk];
        }
#pragma unroll
        for (int i = 0; i < 16; i++) {
            int lin = t + i * 256;           // c*32 + kk
            int c = lin >> 5, kk = lin & 31;
            Ws[c][kk] = w_c[(size_t)(ch * 128 + c) * 128 + k0 + kk];
        }
        __syncthreads();
#pragma unroll
        for (int k = 0; k < 32; k++) {
            float w[8], a[8];
#pragma unroll
            for (int i = 0; i < 8; i++) w[i] = Ws[tc * 8 + i][k];
#pragma unroll
            for (int j = 0; j < 8; j++) a[j] = As[k][tmn * 8 + j];
#pragma unroll
            for (int i = 0; i < 8; i++)
#pragma unroll
                for (int j = 0; j < 8; j++) acc[i][j] += w[i] * a[j];
        }
        __syncthreads();
    }

    float* out = g_Wb + (size_t)b * 256 * MED + (size_t)ch * 128 * MED;
#pragma unroll
    for (int i = 0; i < 8; i++)
#pragma unroll
        for (int j = 0; j < 8; j++)
            out[(size_t)(tc * 8 + i) * MED + tmn * 8 + j] = acc[i][j];
}

// ---------------- K6: result = gamma*relu(Wb @ o + b_c) + x ----------------
// grid (NPIX/128, 256/128, B), block 256
__global__ __launch_bounds__(256, 2)
void k_gemm_out(const float* __restrict__ x, const float* __restrict__ b_c,
                const float* __restrict__ gamma, float* __restrict__ out) {
    __shared__ float As[16][132];   // As[k][c]
    __shared__ float Bs[16][132];   // Bs[k][n]
    const int b    = blockIdx.z;
    const int row0 = blockIdx.y * 128;   // c
    const int col0 = blockIdx.x * 128;   // n
    const float* A = g_Wb + (size_t)b * 256 * MED;
    const float* B = g_ov + (size_t)b * 256 * NPIX;   // o rows 0..127
    const int t = threadIdx.x;
    const int tm = t >> 4, tn = t & 15;

    float acc[8][8];
#pragma unroll
    for (int i = 0; i < 8; i++)
#pragma unroll
        for (int j = 0; j < 8; j++) acc[i][j] = 0.f;

    for (int kk = 0; kk < 128; kk += 16) {
#pragma unroll
        for (int i = 0; i < 2; i++) {
            int lin = t * 2 + i;
            int m = lin >> 2, kq = lin & 3;
            float4 v4 = *(const float4*)(A + (size_t)(row0 + m) * 128 + kk + kq * 4);
            As[kq * 4 + 0][m] = v4.x;
            As[kq * 4 + 1][m] = v4.y;
            As[kq * 4 + 2][m] = v4.z;
            As[kq * 4 + 3][m] = v4.w;
        }
#pragma unroll
        for (int i = 0; i < 2; i++) {
            int lin = t + i * 256;
            int k = lin >> 5, nq = lin & 31;
            float4 v4 = *(const float4*)(B + (size_t)(kk + k) * NPIX + col0 + nq * 4);
            *(float4*)&Bs[k][nq * 4] = v4;
        }
        __syncthreads();
#pragma unroll
        for (int k = 0; k < 16; k++) {
            float a[8], bb[8];
#pragma unroll
            for (int i = 0; i < 8; i++) a[i] = As[k][tm * 8 + i];
#pragma unroll
            for (int j = 0; j < 8; j++) bb[j] = Bs[k][tn * 8 + j];
#pragma unroll
            for (int i = 0; i < 8; i++)
#pragma unroll
                for (int j = 0; j < 8; j++) acc[i][j] += a[i] * bb[j];
        }
        __syncthreads();
    }

    const float g = gamma[0];
#pragma unroll
    for (int i = 0; i < 8; i++) {
        int c = row0 + tm * 8 + i;
        float bc = b_c[c];
        const float* xp = x + ((size_t)b * CIN + c) * NPIX + col0 + tn * 8;
        float4 x0 = *(const float4*)xp;
        float4 x1 = *(const float4*)(xp + 4);
        float4 o0, o1;
        o0.x = fmaxf(acc[i][0] + bc, 0.f) * g + x0.x;
        o0.y = fmaxf(acc[i][1] + bc, 0.f) * g + x0.y;
        o0.z = fmaxf(acc[i][2] + bc, 0.f) * g + x0.z;
        o0.w = fmaxf(acc[i][3] + bc, 0.f) * g + x0.w;
        o1.x = fmaxf(acc[i][4] + bc, 0.f) * g + x1.x;
        o1.y = fmaxf(acc[i][5] + bc, 0.f) * g + x1.y;
        o1.z = fmaxf(acc[i][6] + bc, 0.f) * g + x1.z;
        o1.w = fmaxf(acc[i][7] + bc, 0.f) * g + x1.w;
        float* op = out + ((size_t)b * CIN + c) * NPIX + col0 + tn * 8;
        *(float4*)op = o0;
        *(float4*)(op + 4) = o1;
    }
}

// ---------------- launch ----------------
extern "C" void kernel_launch(void* const* d_in, const int* in_sizes, int n_in,
                              void* d_out, int out_size) {
    const float* x     = (const float*)d_in[0];
    const float* w_o   = (const float*)d_in[1];
    const float* b_o   = (const float*)d_in[2];
    const float* w_v   = (const float*)d_in[3];
    const float* b_v   = (const float*)d_in[4];
    const float* w_c   = (const float*)d_in[5];
    const float* b_c   = (const float*)d_in[6];
    const float* gamma = (const float*)d_in[7];
    float* out = (float*)d_out;

    k_prep<<<128, 256>>>(w_o, b_o, w_v, b_v);
    k_gemm_ov<<<dim3(NPIX / 128, 2, BATCH), 256>>>(x);
    k_softmax_rows<<<BATCH * MED, 256>>>();
    k_softmax_cols<<<BATCH * NPIX / 256, 256>>>();
    k_gemmA_part<<<dim3(16, BATCH), 256>>>();
    k_reduceA<<<BATCH, 256>>>();
    k_gemmWb<<<dim3(BATCH, 2), 256>>>(w_c);
    k_gemm_out<<<dim3(NPIX / 128, 2, BATCH), 256>>>(x, b_c, gamma, out);
}

// round 3
// speedup vs baseline: 1.8494x; 1.8494x over previous
#include <cuda_runtime.h>
#include <cstdint>

// Problem constants
#define BATCH 16
#define CIN   256
#define MED   128
#define NPIX  4096   // 64*64

// ---------------- scratch (static __device__, no allocations) ----------------
__device__ float g_W[256 * 256];              // stacked [w_o; w_v] (tf32-rounded), [256][256]
__device__ float g_bias[256];                 // stacked [b_o; b_v]
__device__ float g_ov[BATCH * 256 * NPIX];    // rows 0..127 = o, 128..255 = v
__device__ float g_xv[BATCH * MED * NPIX];    // softmax over N of v
__device__ float g_xs[BATCH * MED * NPIX];    // softmax over M of v
__device__ float g_Apart[BATCH * 16 * MED * MED];
__device__ float g_A[BATCH * MED * MED];
__device__ float g_Wb[BATCH * 256 * MED];     // Wb[b][c][m]

// ======================= helpers =======================
__device__ __forceinline__ uint32_t smem_u32(const void* p) {
    uint32_t a;
    asm("{ .reg .u64 t; cvta.to.shared.u64 t, %1; cvt.u32.u64 %0, t; }" : "=r"(a) : "l"(p));
    return a;
}

#define CP16(dst, src) \
    asm volatile("cp.async.ca.shared.global [%0], [%1], 16;" :: "r"(dst), "l"(src) : "memory")
#define CP_COMMIT asm volatile("cp.async.commit_group;" ::: "memory")
#define CP_WAIT1  asm volatile("cp.async.wait_group 1;" ::: "memory")
#define CP_WAIT0  asm volatile("cp.async.wait_group 0;" ::: "memory")

__device__ __forceinline__ void mma_tf32(float* d, const uint32_t* a, const uint32_t* b) {
    asm volatile(
        "mma.sync.aligned.m16n8k8.row.col.f32.tf32.tf32.f32 "
        "{%0,%1,%2,%3}, {%4,%5,%6,%7}, {%8,%9}, {%0,%1,%2,%3};"
        : "+f"(d[0]), "+f"(d[1]), "+f"(d[2]), "+f"(d[3])
        : "r"(a[0]), "r"(a[1]), "r"(a[2]), "r"(a[3]), "r"(b[0]), "r"(b[1]));
}

// SMEM tile layout constants (floats)
#define A_STRIDE 36     // 32 k + 4 pad  -> conflict-free a-frag loads
#define B_STRIDE 136    // 128 n + 8 pad -> conflict-free b-frag loads
#define A_TILE_F (128 * A_STRIDE)   // 4608
#define B_TILE_F (32 * B_STRIDE)    // 4352
#define SMEM_BYTES ((2 * A_TILE_F + 2 * B_TILE_F) * 4)   // 71680

// one k-tile (K=32) of warp-level mma compute
__device__ __forceinline__ void compute_tile(const float* As_, const float* Bs_,
                                             int lane, int wm, int wn, float acc[2][8][4]) {
    const int lr = lane >> 2, lc = lane & 3;
#pragma unroll
    for (int ks = 0; ks < 4; ks++) {
        const int k0 = ks * 8;
        uint32_t a[2][4];
#pragma unroll
        for (int i = 0; i < 2; i++) {
            const float* ap = As_ + (size_t)(wm + i * 16 + lr) * A_STRIDE + k0 + lc;
            a[i][0] = __float_as_uint(ap[0]);
            a[i][1] = __float_as_uint(ap[8 * A_STRIDE]);
            a[i][2] = __float_as_uint(ap[4]);
            a[i][3] = __float_as_uint(ap[8 * A_STRIDE + 4]);
        }
        uint32_t bb[8][2];
#pragma unroll
        for (int j = 0; j < 8; j++) {
            const float* bp = Bs_ + (size_t)(k0 + lc) * B_STRIDE + wn + j * 8 + lr;
            bb[j][0] = __float_as_uint(bp[0]);
            bb[j][1] = __float_as_uint(bp[4 * B_STRIDE]);
        }
#pragma unroll
        for (int i = 0; i < 2; i++)
#pragma unroll
            for (int j = 0; j < 8; j++)
                mma_tf32(acc[i][j], a[i], bb[j]);
    }
}

// ---------------- prep: stack weights/bias, round to tf32 (rna) ----------------
__global__ void k_prep(const float* __restrict__ w_o, const float* __restrict__ b_o,
                       const float* __restrict__ w_v, const float* __restrict__ b_v) {
    int i = blockIdx.x * blockDim.x + threadIdx.x;
    if (i < 128 * 256) {
        uint32_t uo, uv;
        float vo = w_o[i], vv = w_v[i];
        asm("cvt.rna.tf32.f32 %0, %1;" : "=r"(uo) : "f"(vo));
        asm("cvt.rna.tf32.f32 %0, %1;" : "=r"(uv) : "f"(vv));
        g_W[i] = __uint_as_float(uo);
        g_W[128 * 256 + i] = __uint_as_float(uv);
    }
    if (i < 128) {
        g_bias[i] = b_o[i];
        g_bias[128 + i] = b_v[i];
    }
}

// ---------------- K1: ov = W_stack @ x + bias  (tf32 mma.sync) ----------------
// grid (NPIX/128, 256/128, B), block 256 (8 warps, 4m x 2n)
__global__ __launch_bounds__(256)
void k1_mma_tf32(const float* __restrict__ x) {
    extern __shared__ float sm[];
    float* AsBase = sm;                       // 2 x A_TILE_F
    float* BsBase = sm + 2 * A_TILE_F;        // 2 x B_TILE_F
    const uint32_t sA_u32 = smem_u32(AsBase);
    const uint32_t sB_u32 = smem_u32(BsBase);

    const int t = threadIdx.x;
    const int lane = t & 31, wid = t >> 5;
    const int wm = (wid & 3) * 32, wn = (wid >> 2) * 64;
    const int b = blockIdx.z;
    const int m0 = blockIdx.y * 128;
    const int col0 = blockIdx.x * 128;
    const float* Xb = x + (size_t)b * CIN * NPIX;

    float acc[2][8][4];
#pragma unroll
    for (int i = 0; i < 2; i++)
#pragma unroll
        for (int j = 0; j < 8; j++)
#pragma unroll
            for (int r = 0; r < 4; r++) acc[i][j][r] = 0.f;

    // prologue: tile 0
    {
        const int kc = 0;
#pragma unroll
        for (int i = 0; i < 4; i++) {
            int lin = t + i * 256;
            int r = lin >> 3, q = lin & 7;
            CP16(sA_u32 + (uint32_t)(r * A_STRIDE + q * 4) * 4,
                 g_W + (size_t)(m0 + r) * 256 + kc + q * 4);
        }
#pragma unroll
        for (int i = 0; i < 4; i++) {
            int lin = t + i * 256;
            int kk = lin >> 5, nq = lin & 31;
            CP16(sB_u32 + (uint32_t)(kk * B_STRIDE + nq * 4) * 4,
                 Xb + (size_t)(kc + kk) * NPIX + col0 + nq * 4);
        }
        CP_COMMIT;
    }

    for (int kt = 0; kt < 8; kt++) {
        const int buf = kt & 1;
        if (kt < 7) {
            const int nbuf = (kt + 1) & 1;
            const int kc = (kt + 1) * 32;
#pragma unroll
            for (int i = 0; i < 4; i++) {
                int lin = t + i * 256;
                int r = lin >> 3, q = lin & 7;
                CP16(sA_u32 + (uint32_t)(nbuf * A_TILE_F + r * A_STRIDE + q * 4) * 4,
                     g_W + (size_t)(m0 + r) * 256 + kc + q * 4);
            }
#pragma unroll
            for (int i = 0; i < 4; i++) {
                int lin = t + i * 256;
                int kk = lin >> 5, nq = lin & 31;
                CP16(sB_u32 + (uint32_t)(nbuf * B_TILE_F + kk * B_STRIDE + nq * 4) * 4,
                     Xb + (size_t)(kc + kk) * NPIX + col0 + nq * 4);
            }
            CP_COMMIT;
            CP_WAIT1;
        } else {
            CP_WAIT0;
        }
        __syncthreads();
        compute_tile(AsBase + buf * A_TILE_F, BsBase + buf * B_TILE_F, lane, wm, wn, acc);
        __syncthreads();
    }

    // epilogue: + bias, store to g_ov[m][pix]
    float* dst = g_ov + (size_t)b * 256 * NPIX;
    const int lr = lane >> 2, lc = lane & 3;
#pragma unroll
    for (int i = 0; i < 2; i++) {
        int r1 = m0 + wm + i * 16 + lr;
        int r2 = r1 + 8;
        float b1 = g_bias[r1], b2 = g_bias[r2];
#pragma unroll
        for (int j = 0; j < 8; j++) {
            int col = col0 + wn + j * 8 + lc * 2;
            float2 v1 = {acc[i][j][0] + b1, acc[i][j][1] + b1};
            float2 v2 = {acc[i][j][2] + b2, acc[i][j][3] + b2};
            *(float2*)(dst + (size_t)r1 * NPIX + col) = v1;
            *(float2*)(dst + (size_t)r2 * NPIX + col) = v2;
        }
    }
}

// ---------------- K2: row softmax of v (over N=4096) -> g_xv ----------------
__global__ void k_softmax_rows() {
    const int bm = blockIdx.x;
    const int b = bm >> 7, m = bm & 127;
    const float* row = g_ov + (size_t)b * 256 * NPIX + (size_t)(128 + m) * NPIX;
    float* out = g_xv + (size_t)bm * NPIX;

    __shared__ float buf[4096];
    __shared__ float red[9];
    const int t = threadIdx.x;

    float lmax = -1e30f;
    for (int i = t; i < 4096; i += 256) {
        float v = row[i];
        buf[i] = v;
        lmax = fmaxf(lmax, v);
    }
#pragma unroll
    for (int o = 16; o; o >>= 1) lmax = fmaxf(lmax, __shfl_xor_sync(~0u, lmax, o));
    if ((t & 31) == 0) red[t >> 5] = lmax;
    __syncthreads();
    float mx = fmaxf(fmaxf(fmaxf(red[0], red[1]), fmaxf(red[2], red[3])),
                     fmaxf(fmaxf(red[4], red[5]), fmaxf(red[6], red[7])));
    __syncthreads();

    float lsum = 0.f;
    for (int i = t; i < 4096; i += 256) {
        float e = __expf(buf[i] - mx);
        buf[i] = e;
        lsum += e;
    }
#pragma unroll
    for (int o = 16; o; o >>= 1) lsum += __shfl_xor_sync(~0u, lsum, o);
    if ((t & 31) == 0) red[t >> 5] = lsum;
    __syncthreads();
    float inv = 1.f / (red[0] + red[1] + red[2] + red[3] + red[4] + red[5] + red[6] + red[7]);

    for (int i = t; i < 4096; i += 256) out[i] = buf[i] * inv;
}

// ---------------- K3 v2: col softmax of v (over M=128) -> g_xs ----------------
__global__ __launch_bounds__(256)
void k_softmax_cols_v2() {
    __shared__ float vb[128][68];
    __shared__ float redm[4][64], reds[4][64];
    const int blk = blockIdx.x;
    const int b = blk >> 6, n0 = (blk & 63) * 64;
    const float* vbase = g_ov + ((size_t)b * 256 + 128) * NPIX + n0;
    const int t = threadIdx.x;

#pragma unroll
    for (int i = 0; i < 8; i++) {
        int lin = t + i * 256;
        int r = lin >> 4, q = lin & 15;
        float4 v = *(const float4*)(vbase + (size_t)r * NPIX + q * 4);
        *(float4*)&vb[r][q * 4] = v;
    }
    __syncthreads();

    const int pix = t & 63, quar = t >> 6;
    float mx = -1e30f;
#pragma unroll 8
    for (int i = 0; i < 32; i++) mx = fmaxf(mx, vb[quar * 32 + i][pix]);
    redm[quar][pix] = mx;
    __syncthreads();
    mx = fmaxf(fmaxf(redm[0][pix], redm[1][pix]), fmaxf(redm[2][pix], redm[3][pix]));

    float s = 0.f;
#pragma unroll 8
    for (int i = 0; i < 32; i++) s += __expf(vb[quar * 32 + i][pix] - mx);
    reds[quar][pix] = s;
    __syncthreads();
    float inv = 1.f / (reds[0][pix] + reds[1][pix] + reds[2][pix] + reds[3][pix]);

    float* out = g_xs + (size_t)b * MED * NPIX + n0 + pix;
#pragma unroll 8
    for (int i = 0; i < 32; i++) {
        int m = quar * 32 + i;
        out[(size_t)m * NPIX] = __expf(vb[m][pix] - mx) * inv;
    }
}

// ---------------- K4: A partials: A[b] = x_v @ x_s^T, split-K over N ----------------
__global__ __launch_bounds__(256, 2)
void k_gemmA_part() {
    __shared__ float XV[16][132];
    __shared__ float XS[16][132];
    const int split = blockIdx.x;
    const int b = blockIdx.y;
    const int n0 = split * 256;
    const float* xv = g_xv + (size_t)b * MED * NPIX;
    const float* xs = g_xs + (size_t)b * MED * NPIX;
    const int t = threadIdx.x;
    const int tm = t >> 4, tn = t & 15;

    float acc[8][8];
#pragma unroll
    for (int i = 0; i < 8; i++)
#pragma unroll
        for (int j = 0; j < 8; j++) acc[i][j] = 0.f;

    for (int nn = 0; nn < 256; nn += 16) {
#pragma unroll
        for (int i = 0; i < 8; i++) {
            int lin = t + i * 256;
            int m = lin >> 4, nt = lin & 15;
            XV[nt][m] = xv[(size_t)m * NPIX + n0 + nn + nt];
            XS[nt][m] = xs[(size_t)m * NPIX + n0 + nn + nt];
        }
        __syncthreads();
#pragma unroll
        for (int k = 0; k < 16; k++) {
            float a[8], s[8];
#pragma unroll
            for (int i = 0; i < 8; i++) a[i] = XV[k][tm * 8 + i];
#pragma unroll
            for (int j = 0; j < 8; j++) s[j] = XS[k][tn * 8 + j];
#pragma unroll
            for (int i = 0; i < 8; i++)
#pragma unroll
                for (int j = 0; j < 8; j++) acc[i][j] += a[i] * s[j];
        }
        __syncthreads();
    }

    float* out = g_Apart + ((size_t)b * 16 + split) * (MED * MED);
#pragma unroll
    for (int i = 0; i < 8; i++)
#pragma unroll
        for (int j = 0; j < 8; j++)
            out[(size_t)(tm * 8 + i) * MED + tn * 8 + j] = acc[i][j];
}

// ---------------- K4b: reduce partials -> g_A ----------------
__global__ void k_reduceA() {
    const int b = blockIdx.x;
    for (int idx = threadIdx.x; idx < MED * MED; idx += 256) {
        float s = 0.f;
#pragma unroll
        for (int p = 0; p < 16; p++)
            s += g_Apart[((size_t)b * 16 + p) * (MED * MED) + idx];
        g_A[(size_t)b * MED * MED + idx] = s;
    }
}

// ---------------- K5: Wb[b][c][m] = sum_k w_c[c][k] * A[b][m][k] ----------------
__global__ __launch_bounds__(256, 2)
void k_gemmWb(const float* __restrict__ w_c) {
    __shared__ float As_[32][136];
    __shared__ float Ws[128][33];
    const int b = blockIdx.x;
    const int ch = blockIdx.y;
    const float* Ab = g_A + (size_t)b * MED * MED;
    const int t = threadIdx.x;
    const int tc = t >> 4, tmn = t & 15;

    float acc[8][8];
#pragma unroll
    for (int i = 0; i < 8; i++)
#pragma unroll
        for (int j = 0; j < 8; j++) acc[i][j] = 0.f;

    for (int k0 = 0; k0 < 128; k0 += 32) {
#pragma unroll
        for (int i = 0; i < 16; i++) {
            int lin = t + i * 256;
            int m = lin >> 5, kk = lin & 31;
            As_[kk][m] = Ab[(size_t)m * 128 + k0 + kk];
        }
#pragma unroll
        for (int i = 0; i < 16; i++) {
            int lin = t + i * 256;
            int c = lin >> 5, kk = lin & 31;
            Ws[c][kk] = w_c[(size_t)(ch * 128 + c) * 128 + k0 + kk];
        }
        __syncthreads();
#pragma unroll
        for (int k = 0; k < 32; k++) {
            float w[8], a[8];
#pragma unroll
            for (int i = 0; i < 8; i++) w[i] = Ws[tc * 8 + i][k];
#pragma unroll
            for (int j = 0; j < 8; j++) a[j] = As_[k][tmn * 8 + j];
#pragma unroll
            for (int i = 0; i < 8; i++)
#pragma unroll
                for (int j = 0; j < 8; j++) acc[i][j] += w[i] * a[j];
        }
        __syncthreads();
    }

    float* out = g_Wb + (size_t)b * 256 * MED + (size_t)ch * 128 * MED;
#pragma unroll
    for (int i = 0; i < 8; i++)
#pragma unroll
        for (int j = 0; j < 8; j++)
            out[(size_t)(tc * 8 + i) * MED + tmn * 8 + j] = acc[i][j];
}

// ---------------- K6: result = gamma*relu(Wb @ o + b_c) + x  (tf32 mma.sync) ----------------
// grid (NPIX/128, 256/128, B), block 256
__global__ __launch_bounds__(256)
void k6_mma_tf32(const float* __restrict__ x, const float* __restrict__ b_c,
                 const float* __restrict__ gamma, float* __restrict__ outp) {
    extern __shared__ float sm[];
    float* AsBase = sm;
    float* BsBase = sm + 2 * A_TILE_F;
    const uint32_t sA_u32 = smem_u32(AsBase);
    const uint32_t sB_u32 = smem_u32(BsBase);

    const int t = threadIdx.x;
    const int lane = t & 31, wid = t >> 5;
    const int wm = (wid & 3) * 32, wn = (wid >> 2) * 64;
    const int b = blockIdx.z;
    const int m0 = blockIdx.y * 128;          // c offset
    const int col0 = blockIdx.x * 128;        // n offset
    const float* Ab = g_Wb + (size_t)b * 256 * MED;       // [c][k=128]
    const float* Ob = g_ov + (size_t)b * 256 * NPIX;      // o rows 0..127

    float acc[2][8][4];
#pragma unroll
    for (int i = 0; i < 2; i++)
#pragma unroll
        for (int j = 0; j < 8; j++)
#pragma unroll
            for (int r = 0; r < 4; r++) acc[i][j][r] = 0.f;

    // prologue: tile 0
    {
        const int kc = 0;
#pragma unroll
        for (int i = 0; i < 4; i++) {
            int lin = t + i * 256;
            int r = lin >> 3, q = lin & 7;
            CP16(sA_u32 + (uint32_t)(r * A_STRIDE + q * 4) * 4,
                 Ab + (size_t)(m0 + r) * 128 + kc + q * 4);
        }
#pragma unroll
        for (int i = 0; i < 4; i++) {
            int lin = t + i * 256;
            int kk = lin >> 5, nq = lin & 31;
            CP16(sB_u32 + (uint32_t)(kk * B_STRIDE + nq * 4) * 4,
                 Ob + (size_t)(kc + kk) * NPIX + col0 + nq * 4);
        }
        CP_COMMIT;
    }

    for (int kt = 0; kt < 4; kt++) {
        const int buf = kt & 1;
        if (kt < 3) {
            const int nbuf = (kt + 1) & 1;
            const int kc = (kt + 1) * 32;
#pragma unroll
            for (int i = 0; i < 4; i++) {
                int lin = t + i * 256;
                int r = lin >> 3, q = lin & 7;
                CP16(sA_u32 + (uint32_t)(nbuf * A_TILE_F + r * A_STRIDE + q * 4) * 4,
                     Ab + (size_t)(m0 + r) * 128 + kc + q * 4);
            }
#pragma unroll
            for (int i = 0; i < 4; i++) {
                int lin = t + i * 256;
                int kk = lin >> 5, nq = lin & 31;
                CP16(sB_u32 + (uint32_t)(nbuf * B_TILE_F + kk * B_STRIDE + nq * 4) * 4,
                     Ob + (size_t)(kc + kk) * NPIX + col0 + nq * 4);
            }
            CP_COMMIT;
            CP_WAIT1;
        } else {
            CP_WAIT0;
        }
        __syncthreads();
        compute_tile(AsBase + buf * A_TILE_F, BsBase + buf * B_TILE_F, lane, wm, wn, acc);
        __syncthreads();
    }

    // epilogue: relu, gamma, residual
    const float g = gamma[0];
    const int lr = lane >> 2, lc = lane & 3;
#pragma unroll
    for (int i = 0; i < 2; i++) {
        int c1 = m0 + wm + i * 16 + lr;
        int c2 = c1 + 8;
        float bc1 = b_c[c1], bc2 = b_c[c2];
#pragma unroll
        for (int j = 0; j < 8; j++) {
            int col = col0 + wn + j * 8 + lc * 2;
            const float* xp1 = x + ((size_t)b * CIN + c1) * NPIX + col;
            const float* xp2 = x + ((size_t)b * CIN + c2) * NPIX + col;
            float2 xv1 = *(const float2*)xp1;
            float2 xv2 = *(const float2*)xp2;
            float2 o1, o2;
            o1.x = fmaxf(acc[i][j][0] + bc1, 0.f) * g + xv1.x;
            o1.y = fmaxf(acc[i][j][1] + bc1, 0.f) * g + xv1.y;
            o2.x = fmaxf(acc[i][j][2] + bc2, 0.f) * g + xv2.x;
            o2.y = fmaxf(acc[i][j][3] + bc2, 0.f) * g + xv2.y;
            *(float2*)(outp + ((size_t)b * CIN + c1) * NPIX + col) = o1;
            *(float2*)(outp + ((size_t)b * CIN + c2) * NPIX + col) = o2;
        }
    }
}

// ---------------- launch ----------------
extern "C" void kernel_launch(void* const* d_in, const int* in_sizes, int n_in,
                              void* d_out, int out_size) {
    const float* x     = (const float*)d_in[0];
    const float* w_o   = (const float*)d_in[1];
    const float* b_o   = (const float*)d_in[2];
    const float* w_v   = (const float*)d_in[3];
    const float* b_v   = (const float*)d_in[4];
    const float* w_c   = (const float*)d_in[5];
    const float* b_c   = (const float*)d_in[6];
    const float* gamma = (const float*)d_in[7];
    float* out = (float*)d_out;

    cudaFuncSetAttribute(k1_mma_tf32, cudaFuncAttributeMaxDynamicSharedMemorySize, SMEM_BYTES);
    cudaFuncSetAttribute(k6_mma_tf32, cudaFuncAttributeMaxDynamicSharedMemorySize, SMEM_BYTES);

    k_prep<<<128, 256>>>(w_o, b_o, w_v, b_v);
    k1_mma_tf32<<<dim3(NPIX / 128, 2, BATCH), 256, SMEM_BYTES>>>(x);
    k_softmax_rows<<<BATCH * MED, 256>>>();
    k_softmax_cols_v2<<<BATCH * NPIX / 64, 256>>>();
    k_gemmA_part<<<dim3(16, BATCH), 256>>>();
    k_reduceA<<<BATCH, 256>>>();
    k_gemmWb<<<dim3(BATCH, 2), 256>>>(w_c);
    k6_mma_tf32<<<dim3(NPIX / 128, 2, BATCH), 256, SMEM_BYTES>>>(x, b_c, gamma, out);
}

// round 5
// speedup vs baseline: 2.5017x; 1.3527x over previous
#include <cuda_runtime.h>
#include <cstdint>

#define BATCH 16
#define CIN   256
#define MED   128
#define NPIX  4096

// ---------------- scratch ----------------
__device__ float g_W[256 * 256];
__device__ float g_bias[256];
__device__ float g_ov[BATCH * 256 * NPIX];        // rows 0..127 = o, 128..255 = v
__device__ float g_h[BATCH * NPIX];               // 1 / col-sum of e^v
__device__ float g_rowpart[BATCH * MED * 64];     // partial row sums of e^v
__device__ float g_alpha[BATCH * MED];            // 1 / row-sum of e^v
__device__ float g_Apart[BATCH * 8 * MED * MED];  // split-K partials of S
__device__ float g_Wb[BATCH * 256 * MED];

// ======================= helpers =======================
__device__ __forceinline__ uint32_t smem_u32(const void* p) {
    uint32_t a;
    asm("{ .reg .u64 t; cvta.to.shared.u64 t, %1; cvt.u32.u64 %0, t; }" : "=r"(a) : "l"(p));
    return a;
}

#define CP16(dst, src) \
    asm volatile("cp.async.ca.shared.global [%0], [%1], 16;" :: "r"(dst), "l"(src) : "memory")
#define CP_COMMIT asm volatile("cp.async.commit_group;" ::: "memory")
#define CP_WAIT1  asm volatile("cp.async.wait_group 1;" ::: "memory")
#define CP_WAIT0  asm volatile("cp.async.wait_group 0;" ::: "memory")

__device__ __forceinline__ void mma_tf32(float* d, const uint32_t* a, const uint32_t* b) {
    asm volatile(
        "mma.sync.aligned.m16n8k8.row.col.f32.tf32.tf32.f32 "
        "{%0,%1,%2,%3}, {%4,%5,%6,%7}, {%8,%9}, {%0,%1,%2,%3};"
        : "+f"(d[0]), "+f"(d[1]), "+f"(d[2]), "+f"(d[3])
        : "r"(a[0]), "r"(a[1]), "r"(a[2]), "r"(a[3]), "r"(b[0]), "r"(b[1]));
}

#define A_STRIDE 36
#define B_STRIDE 136
#define A_TILE_F (128 * A_STRIDE)
#define B_TILE_F (32 * B_STRIDE)
#define SMEM_BYTES ((2 * A_TILE_F + 2 * B_TILE_F) * 4)

// k-tile (K=32): A in [m][k] stride-36, B in [k][n] stride-136
__device__ __forceinline__ void compute_tile(const float* As_, const float* Bs_,
                                             int lane, int wm, int wn, float acc[2][8][4]) {
    const int lr = lane >> 2, lc = lane & 3;
#pragma unroll
    for (int ks = 0; ks < 4; ks++) {
        const int k0 = ks * 8;
        uint32_t a[2][4];
#pragma unroll
        for (int i = 0; i < 2; i++) {
            const float* ap = As_ + (size_t)(wm + i * 16 + lr) * A_STRIDE + k0 + lc;
            a[i][0] = __float_as_uint(ap[0]);
            a[i][1] = __float_as_uint(ap[8 * A_STRIDE]);
            a[i][2] = __float_as_uint(ap[4]);
            a[i][3] = __float_as_uint(ap[8 * A_STRIDE + 4]);
        }
        uint32_t bb[8][2];
#pragma unroll
        for (int j = 0; j < 8; j++) {
            const float* bp = Bs_ + (size_t)(k0 + lc) * B_STRIDE + wn + j * 8 + lr;
            bb[j][0] = __float_as_uint(bp[0]);
            bb[j][1] = __float_as_uint(bp[4 * B_STRIDE]);
        }
#pragma unroll
        for (int i = 0; i < 2; i++)
#pragma unroll
            for (int j = 0; j < 8; j++)
                mma_tf32(acc[i][j], a[i], bb[j]);
    }
}

// k-tile (K=32): BOTH operands in row-major [row][k] stride-36 (K-major)
__device__ __forceinline__ void compute_tile_kk(const float* As_, const float* Bs_,
                                                int lane, int wm, int wn, float acc[2][8][4]) {
    const int lr = lane >> 2, lc = lane & 3;
#pragma unroll
    for (int ks = 0; ks < 4; ks++) {
        const int k0 = ks * 8;
        uint32_t a[2][4];
#pragma unroll
        for (int i = 0; i < 2; i++) {
            const float* ap = As_ + (size_t)(wm + i * 16 + lr) * A_STRIDE + k0 + lc;
            a[i][0] = __float_as_uint(ap[0]);
            a[i][1] = __float_as_uint(ap[8 * A_STRIDE]);
            a[i][2] = __float_as_uint(ap[4]);
            a[i][3] = __float_as_uint(ap[8 * A_STRIDE + 4]);
        }
        uint32_t bb[8][2];
#pragma unroll
        for (int j = 0; j < 8; j++) {
            const float* bp = Bs_ + (size_t)(wn + j * 8 + lr) * A_STRIDE + k0 + lc;
            bb[j][0] = __float_as_uint(bp[0]);
            bb[j][1] = __float_as_uint(bp[4]);
        }
#pragma unroll
        for (int i = 0; i < 2; i++)
#pragma unroll
            for (int j = 0; j < 8; j++)
                mma_tf32(acc[i][j], a[i], bb[j]);
    }
}

// ---------------- prep ----------------
__global__ void k_prep(const float* __restrict__ w_o, const float* __restrict__ b_o,
                       const float* __restrict__ w_v, const float* __restrict__ b_v) {
    int i = blockIdx.x * blockDim.x + threadIdx.x;
    if (i < 128 * 256) {
        uint32_t uo, uv;
        float vo = w_o[i], vv = w_v[i];
        asm("cvt.rna.tf32.f32 %0, %1;" : "=r"(uo) : "f"(vo));
        asm("cvt.rna.tf32.f32 %0, %1;" : "=r"(uv) : "f"(vv));
        g_W[i] = __uint_as_float(uo);
        g_W[128 * 256 + i] = __uint_as_float(uv);
    }
    if (i < 128) {
        g_bias[i] = b_o[i];
        g_bias[128 + i] = b_v[i];
    }
}

// ---------------- K1: ov = W @ x + bias (tf32 mma) ----------------
__global__ __launch_bounds__(256)
void k1_mma_tf32(const float* __restrict__ x) {
    extern __shared__ float sm[];
    float* AsBase = sm;
    float* BsBase = sm + 2 * A_TILE_F;
    const uint32_t sA_u32 = smem_u32(AsBase);
    const uint32_t sB_u32 = smem_u32(BsBase);

    const int t = threadIdx.x;
    const int lane = t & 31, wid = t >> 5;
    const int wm = (wid & 3) * 32, wn = (wid >> 2) * 64;
    const int b = blockIdx.z;
    const int m0 = blockIdx.y * 128;
    const int col0 = blockIdx.x * 128;
    const float* Xb = x + (size_t)b * CIN * NPIX;

    float acc[2][8][4];
#pragma unroll
    for (int i = 0; i < 2; i++)
#pragma unroll
        for (int j = 0; j < 8; j++)
#pragma unroll
            for (int r = 0; r < 4; r++) acc[i][j][r] = 0.f;

    {
#pragma unroll
        for (int i = 0; i < 4; i++) {
            int lin = t + i * 256;
            int r = lin >> 3, q = lin & 7;
            CP16(sA_u32 + (uint32_t)(r * A_STRIDE + q * 4) * 4,
                 g_W + (size_t)(m0 + r) * 256 + q * 4);
        }
#pragma unroll
        for (int i = 0; i < 4; i++) {
            int lin = t + i * 256;
            int kk = lin >> 5, nq = lin & 31;
            CP16(sB_u32 + (uint32_t)(kk * B_STRIDE + nq * 4) * 4,
                 Xb + (size_t)kk * NPIX + col0 + nq * 4);
        }
        CP_COMMIT;
    }

    for (int kt = 0; kt < 8; kt++) {
        const int buf = kt & 1;
        if (kt < 7) {
            const int nbuf = (kt + 1) & 1;
            const int kc = (kt + 1) * 32;
#pragma unroll
            for (int i = 0; i < 4; i++) {
                int lin = t + i * 256;
                int r = lin >> 3, q = lin & 7;
                CP16(sA_u32 + (uint32_t)(nbuf * A_TILE_F + r * A_STRIDE + q * 4) * 4,
                     g_W + (size_t)(m0 + r) * 256 + kc + q * 4);
            }
#pragma unroll
            for (int i = 0; i < 4; i++) {
                int lin = t + i * 256;
                int kk = lin >> 5, nq = lin & 31;
                CP16(sB_u32 + (uint32_t)(nbuf * B_TILE_F + kk * B_STRIDE + nq * 4) * 4,
                     Xb + (size_t)(kc + kk) * NPIX + col0 + nq * 4);
            }
            CP_COMMIT;
            CP_WAIT1;
        } else {
            CP_WAIT0;
        }
        __syncthreads();
        compute_tile(AsBase + buf * A_TILE_F, BsBase + buf * B_TILE_F, lane, wm, wn, acc);
        __syncthreads();
    }

    float* dst = g_ov + (size_t)b * 256 * NPIX;
    const int lr = lane >> 2, lc = lane & 3;
#pragma unroll
    for (int i = 0; i < 2; i++) {
        int r1 = m0 + wm + i * 16 + lr;
        int r2 = r1 + 8;
        float b1 = g_bias[r1], b2 = g_bias[r2];
#pragma unroll
        for (int j = 0; j < 8; j++) {
            int col = col0 + wn + j * 8 + lc * 2;
            float2 v1 = {acc[i][j][0] + b1, acc[i][j][1] + b1};
            float2 v2 = {acc[i][j][2] + b2, acc[i][j][3] + b2};
            *(float2*)(dst + (size_t)r1 * NPIX + col) = v1;
            *(float2*)(dst + (size_t)r2 * NPIX + col) = v2;
        }
    }
}

// ---------------- stats: h[n]=1/colsum(e^v), rowpart[b][m][nblk] ----------------
// grid (64, 16), block 256; tile v[128][64]
__global__ __launch_bounds__(256)
void k_stats() {
    __shared__ float vb[128][68];
    __shared__ float reds[4][64];
    const int nblk = blockIdx.x, b = blockIdx.y;
    const int n0 = nblk * 64;
    const float* vbase = g_ov + ((size_t)b * 256 + 128) * NPIX + n0;
    const int t = threadIdx.x;

#pragma unroll
    for (int i = 0; i < 8; i++) {
        int lin = t + i * 256;
        int r = lin >> 4, q = lin & 15;
        float4 v = *(const float4*)(vbase + (size_t)r * NPIX + q * 4);
        *(float4*)&vb[r][q * 4] = v;
    }
    __syncthreads();

    // column sums of e^v (store e^v back into tile)
    const int pix = t & 63, quar = t >> 6;
    float s = 0.f;
#pragma unroll 8
    for (int i = 0; i < 32; i++) {
        int m = quar * 32 + i;
        float e = __expf(vb[m][pix]);
        vb[m][pix] = e;
        s += e;
    }
    reds[quar][pix] = s;
    __syncthreads();
    if (quar == 0) {
        float tot = reds[0][pix] + reds[1][pix] + reds[2][pix] + reds[3][pix];
        g_h[(size_t)b * NPIX + n0 + pix] = 1.f / tot;
    }

    // partial row sums: thread -> row t>>1, half t&1
    const int r = t >> 1, half = t & 1;
    float rs = 0.f;
#pragma unroll 8
    for (int i = 0; i < 32; i++) rs += vb[r][half * 32 + i];
    rs += __shfl_xor_sync(~0u, rs, 1);
    if (half == 0)
        g_rowpart[((size_t)b * MED + r) * 64 + nblk] = rs;
}

// ---------------- alpha: 1/rowsum ----------------
__global__ void k_alpha() {
    const int b = blockIdx.x;
    const int m = threadIdx.x;        // 128
    const float* p = g_rowpart + ((size_t)b * MED + m) * 64;
    float s = 0.f;
#pragma unroll
    for (int i = 0; i < 64; i++) s += p[i];
    g_alpha[b * MED + m] = 1.f / s;
}

// ---------------- K4: S partials via tf32 mma on exp tiles ----------------
// grid (8 splits, 16 b), block 256. Each CTA: 128x128 output, 512-long contraction.
#define K4_RSTRIDE 36                     // 144 bytes: 16B-aligned for cp.async
#define K4_RAWF (128 * K4_RSTRIDE)
#define K4_SMEM_F (2 * K4_RAWF + 2 * (128 * A_STRIDE) + 512)
#define K4_SMEM_BYTES (K4_SMEM_F * 4)
__global__ __launch_bounds__(256)
void k4_mma() {
    extern __shared__ float sm4[];
    float* raw = sm4;                          // 2 x 128x36
    float* E   = sm4 + 2 * K4_RAWF;            // 128 x 36
    float* EH  = E + 128 * A_STRIDE;           // 128 x 36
    float* hsh = EH + 128 * A_STRIDE;          // 512
    const uint32_t raw_u32 = smem_u32(raw);

    const int t = threadIdx.x;
    const int lane = t & 31, wid = t >> 5;
    const int wm = (wid & 3) * 32, wn = (wid >> 2) * 64;
    const int split = blockIdx.x, b = blockIdx.y;
    const int n0 = split * 512;
    const float* V = g_ov + ((size_t)b * 256 + 128) * NPIX + n0;

    for (int i = t; i < 512; i += 256) hsh[i] = g_h[(size_t)b * NPIX + n0 + i];

    float acc[2][8][4];
#pragma unroll
    for (int i = 0; i < 2; i++)
#pragma unroll
        for (int j = 0; j < 8; j++)
#pragma unroll
            for (int r = 0; r < 4; r++) acc[i][j][r] = 0.f;

    // prologue: raw[0] <- v[:, 0:32]
#pragma unroll
    for (int i = 0; i < 4; i++) {
        int lin = t + i * 256;
        int r = lin >> 3, q = lin & 7;
        CP16(raw_u32 + (uint32_t)(r * K4_RSTRIDE + q * 4) * 4, V + (size_t)r * NPIX + q * 4);
    }
    CP_COMMIT;

    const int cr = t >> 1, cc0 = (t & 1) * 16;
    for (int s = 0; s < 16; s++) {
        const int buf = s & 1;
        if (s < 15) {
            const int nbuf = (s + 1) & 1;
            const int scol = (s + 1) * 32;
#pragma unroll
            for (int i = 0; i < 4; i++) {
                int lin = t + i * 256;
                int r = lin >> 3, q = lin & 7;
                CP16(raw_u32 + (uint32_t)(nbuf * K4_RAWF + r * K4_RSTRIDE + q * 4) * 4,
                     V + (size_t)r * NPIX + scol + q * 4);
            }
            CP_COMMIT;
            CP_WAIT1;
        } else {
            CP_WAIT0;
        }
        __syncthreads();   // raw ready AND previous mma done reading E/EH
        const float* rb = raw + buf * K4_RAWF;
#pragma unroll
        for (int i = 0; i < 16; i++) {
            int c = cc0 + i;
            float e = __expf(rb[cr * K4_RSTRIDE + c]);
            E[cr * A_STRIDE + c] = e;
            EH[cr * A_STRIDE + c] = e * hsh[s * 32 + c];
        }
        __syncthreads();
        compute_tile_kk(EH, E, lane, wm, wn, acc);
    }

    // store partials
    float* out = g_Apart + ((size_t)b * 8 + split) * (MED * MED);
    const int lr = lane >> 2, lc = lane & 3;
#pragma unroll
    for (int i = 0; i < 2; i++) {
        int r1 = wm + i * 16 + lr, r2 = r1 + 8;
#pragma unroll
        for (int j = 0; j < 8; j++) {
            int col = wn + j * 8 + lc * 2;
            *(float2*)(out + (size_t)r1 * MED + col) = make_float2(acc[i][j][0], acc[i][j][1]);
            *(float2*)(out + (size_t)r2 * MED + col) = make_float2(acc[i][j][2], acc[i][j][3]);
        }
    }
}

// ---------------- Wb fused: Wb[b][c][m] = alpha_m * sum_k w_c[c][k]*S[m][k] ----------------
__global__ __launch_bounds__(256, 2)
void k_gemmWb(const float* __restrict__ w_c) {
    __shared__ float As_[32][136];
    __shared__ float Ws[128][33];
    const int b = blockIdx.x;
    const int ch = blockIdx.y;
    const float* Ap = g_Apart + (size_t)b * 8 * MED * MED;
    const int t = threadIdx.x;
    const int tc = t >> 4, tmn = t & 15;

    float acc[8][8];
#pragma unroll
    for (int i = 0; i < 8; i++)
#pragma unroll
        for (int j = 0; j < 8; j++) acc[i][j] = 0.f;

    for (int k0 = 0; k0 < 128; k0 += 32) {
#pragma unroll
        for (int i = 0; i < 16; i++) {
            int lin = t + i * 256;
            int m = lin >> 5, kk = lin & 31;
            float s = 0.f;
#pragma unroll
            for (int p = 0; p < 8; p++)
                s += Ap[(size_t)p * MED * MED + (size_t)m * 128 + k0 + kk];
            As_[kk][m] = s;
        }
#pragma unroll
        for (int i = 0; i < 16; i++) {
            int lin = t + i * 256;
            int c = lin >> 5, kk = lin & 31;
            Ws[c][kk] = w_c[(size_t)(ch * 128 + c) * 128 + k0 + kk];
        }
        __syncthreads();
#pragma unroll
        for (int k = 0; k < 32; k++) {
            float w[8], a[8];
#pragma unroll
            for (int i = 0; i < 8; i++) w[i] = Ws[tc * 8 + i][k];
#pragma unroll
            for (int j = 0; j < 8; j++) a[j] = As_[k][tmn * 8 + j];
#pragma unroll
            for (int i = 0; i < 8; i++)
#pragma unroll
                for (int j = 0; j < 8; j++) acc[i][j] += w[i] * a[j];
        }
        __syncthreads();
    }

    float alpha[8];
#pragma unroll
    for (int j = 0; j < 8; j++) alpha[j] = g_alpha[b * MED + tmn * 8 + j];

    float* out = g_Wb + (size_t)b * 256 * MED + (size_t)ch * 128 * MED;
#pragma unroll
    for (int i = 0; i < 8; i++)
#pragma unroll
        for (int j = 0; j < 8; j++)
            out[(size_t)(tc * 8 + i) * MED + tmn * 8 + j] = acc[i][j] * alpha[j];
}

// ---------------- K6: gamma*relu(Wb @ o + b_c) + x (tf32 mma) ----------------
__global__ __launch_bounds__(256)
void k6_mma_tf32(const float* __restrict__ x, const float* __restrict__ b_c,
                 const float* __restrict__ gamma, float* __restrict__ outp) {
    extern __shared__ float sm[];
    float* AsBase = sm;
    float* BsBase = sm + 2 * A_TILE_F;
    const uint32_t sA_u32 = smem_u32(AsBase);
    const uint32_t sB_u32 = smem_u32(BsBase);

    const int t = threadIdx.x;
    const int lane = t & 31, wid = t >> 5;
    const int wm = (wid & 3) * 32, wn = (wid >> 2) * 64;
    const int b = blockIdx.z;
    const int m0 = blockIdx.y * 128;
    const int col0 = blockIdx.x * 128;
    const float* Ab = g_Wb + (size_t)b * 256 * MED;
    const float* Ob = g_ov + (size_t)b * 256 * NPIX;

    float acc[2][8][4];
#pragma unroll
    for (int i = 0; i < 2; i++)
#pragma unroll
        for (int j = 0; j < 8; j++)
#pragma unroll
            for (int r = 0; r < 4; r++) acc[i][j][r] = 0.f;

    {
#pragma unroll
        for (int i = 0; i < 4; i++) {
            int lin = t + i * 256;
            int r = lin >> 3, q = lin & 7;
            CP16(sA_u32 + (uint32_t)(r * A_STRIDE + q * 4) * 4,
                 Ab + (size_t)(m0 + r) * 128 + q * 4);
        }
#pragma unroll
        for (int i = 0; i < 4; i++) {
            int lin = t + i * 256;
            int kk = lin >> 5, nq = lin & 31;
            CP16(sB_u32 + (uint32_t)(kk * B_STRIDE + nq * 4) * 4,
                 Ob + (size_t)kk * NPIX + col0 + nq * 4);
        }
        CP_COMMIT;
    }

    for (int kt = 0; kt < 4; kt++) {
        const int buf = kt & 1;
        if (kt < 3) {
            const int nbuf = (kt + 1) & 1;
            const int kc = (kt + 1) * 32;
#pragma unroll
            for (int i = 0; i < 4; i++) {
                int lin = t + i * 256;
                int r = lin >> 3, q = lin & 7;
                CP16(sA_u32 + (uint32_t)(nbuf * A_TILE_F + r * A_STRIDE + q * 4) * 4,
                     Ab + (size_t)(m0 + r) * 128 + kc + q * 4);
            }
#pragma unroll
            for (int i = 0; i < 4; i++) {
                int lin = t + i * 256;
                int kk = lin >> 5, nq = lin & 31;
                CP16(sB_u32 + (uint32_t)(nbuf * B_TILE_F + kk * B_STRIDE + nq * 4) * 4,
                     Ob + (size_t)(kc + kk) * NPIX + col0 + nq * 4);
            }
            CP_COMMIT;
            CP_WAIT1;
        } else {
            CP_WAIT0;
        }
        __syncthreads();
        compute_tile(AsBase + buf * A_TILE_F, BsBase + buf * B_TILE_F, lane, wm, wn, acc);
        __syncthreads();
    }

    const float g = gamma[0];
    const int lr = lane >> 2, lc = lane & 3;
#pragma unroll
    for (int i = 0; i < 2; i++) {
        int c1 = m0 + wm + i * 16 + lr;
        int c2 = c1 + 8;
        float bc1 = b_c[c1], bc2 = b_c[c2];
#pragma unroll
        for (int j = 0; j < 8; j++) {
            int col = col0 + wn + j * 8 + lc * 2;
            float2 xv1 = *(const float2*)(x + ((size_t)b * CIN + c1) * NPIX + col);
            float2 xv2 = *(const float2*)(x + ((size_t)b * CIN + c2) * NPIX + col);
            float2 o1, o2;
            o1.x = fmaxf(acc[i][j][0] + bc1, 0.f) * g + xv1.x;
            o1.y = fmaxf(acc[i][j][1] + bc1, 0.f) * g + xv1.y;
            o2.x = fmaxf(acc[i][j][2] + bc2, 0.f) * g + xv2.x;
            o2.y = fmaxf(acc[i][j][3] + bc2, 0.f) * g + xv2.y;
            *(float2*)(outp + ((size_t)b * CIN + c1) * NPIX + col) = o1;
            *(float2*)(outp + ((size_t)b * CIN + c2) * NPIX + col) = o2;
        }
    }
}

// ---------------- launch ----------------
extern "C" void kernel_launch(void* const* d_in, const int* in_sizes, int n_in,
                              void* d_out, int out_size) {
    const float* x     = (const float*)d_in[0];
    const float* w_o   = (const float*)d_in[1];
    const float* b_o   = (const float*)d_in[2];
    const float* w_v   = (const float*)d_in[3];
    const float* b_v   = (const float*)d_in[4];
    const float* w_c   = (const float*)d_in[5];
    const float* b_c   = (const float*)d_in[6];
    const float* gamma = (const float*)d_in[7];
    float* out = (float*)d_out;

    cudaFuncSetAttribute(k1_mma_tf32, cudaFuncAttributeMaxDynamicSharedMemorySize, SMEM_BYTES);
    cudaFuncSetAttribute(k6_mma_tf32, cudaFuncAttributeMaxDynamicSharedMemorySize, SMEM_BYTES);
    cudaFuncSetAttribute(k4_mma, cudaFuncAttributeMaxDynamicSharedMemorySize, K4_SMEM_BYTES);

    k_prep<<<128, 256>>>(w_o, b_o, w_v, b_v);
    k1_mma_tf32<<<dim3(NPIX / 128, 2, BATCH), 256, SMEM_BYTES>>>(x);
    k_stats<<<dim3(64, BATCH), 256>>>();
    k_alpha<<<BATCH, 128>>>();
    k4_mma<<<dim3(8, BATCH), 256, K4_SMEM_BYTES>>>();
    k_gemmWb<<<dim3(BATCH, 2), 256>>>(w_c);
    k6_mma_tf32<<<dim3(NPIX / 128, 2, BATCH), 256, SMEM_BYTES>>>(x, b_c, gamma, out);
}

// round 6
// speedup vs baseline: 2.8489x; 1.1388x over previous
#include <cuda_runtime.h>
#include <cuda_fp16.h>
#include <cstdint>

#define BATCH 16
#define CIN   256
#define MED   128
#define NPIX  4096

// ---------------- scratch ----------------
__device__ __half g_Wh[256 * 256];                 // stacked [w_o; w_v] half
__device__ float  g_bias[256];
__device__ __half g_xh[(size_t)BATCH * 256 * NPIX];    // x in half
__device__ __half g_oh[(size_t)BATCH * 128 * NPIX];    // o in half (K6 operand)
__device__ float  g_v[(size_t)BATCH * 128 * NPIX];     // v logits fp32
__device__ float  g_h[BATCH * NPIX];               // 1 / col-sum of e^v
__device__ float  g_rowpart[BATCH * MED * 64];     // partial row sums of e^v
__device__ float  g_alpha[BATCH * MED];            // 1 / row-sum of e^v
__device__ float  g_Apart[BATCH * 8 * MED * MED];  // split-K partials of S
__device__ __half g_Wbh[BATCH * 256 * MED];        // Wb half [b][c][m]

// ======================= helpers =======================
__device__ __forceinline__ uint32_t smem_u32(const void* p) {
    uint32_t a;
    asm("{ .reg .u64 t; cvta.to.shared.u64 t, %1; cvt.u32.u64 %0, t; }" : "=r"(a) : "l"(p));
    return a;
}

#define CP16(dst, src) \
    asm volatile("cp.async.ca.shared.global [%0], [%1], 16;" :: "r"(dst), "l"(src) : "memory")
#define CP_COMMIT asm volatile("cp.async.commit_group;" ::: "memory")
#define CP_WAIT1  asm volatile("cp.async.wait_group 1;" ::: "memory")
#define CP_WAIT0  asm volatile("cp.async.wait_group 0;" ::: "memory")

__device__ __forceinline__ void mma_tf32(float* d, const uint32_t* a, const uint32_t* b) {
    asm volatile(
        "mma.sync.aligned.m16n8k8.row.col.f32.tf32.tf32.f32 "
        "{%0,%1,%2,%3}, {%4,%5,%6,%7}, {%8,%9}, {%0,%1,%2,%3};"
        : "+f"(d[0]), "+f"(d[1]), "+f"(d[2]), "+f"(d[3])
        : "r"(a[0]), "r"(a[1]), "r"(a[2]), "r"(a[3]), "r"(b[0]), "r"(b[1]));
}

__device__ __forceinline__ void mma_f16(float* d, const uint32_t* a, const uint32_t* b) {
    asm volatile(
        "mma.sync.aligned.m16n8k16.row.col.f32.f16.f16.f32 "
        "{%0,%1,%2,%3}, {%4,%5,%6,%7}, {%8,%9}, {%0,%1,%2,%3};"
        : "+f"(d[0]), "+f"(d[1]), "+f"(d[2]), "+f"(d[3])
        : "r"(a[0]), "r"(a[1]), "r"(a[2]), "r"(a[3]), "r"(b[0]), "r"(b[1]));
}

__device__ __forceinline__ void ldsm_x4(uint32_t* r, uint32_t a) {
    asm volatile("ldmatrix.sync.aligned.m8n8.x4.shared.b16 {%0,%1,%2,%3}, [%4];"
                 : "=r"(r[0]), "=r"(r[1]), "=r"(r[2]), "=r"(r[3]) : "r"(a));
}
__device__ __forceinline__ void ldsm_x4_t(uint32_t* r, uint32_t a) {
    asm volatile("ldmatrix.sync.aligned.m8n8.x4.trans.shared.b16 {%0,%1,%2,%3}, [%4];"
                 : "=r"(r[0]), "=r"(r[1]), "=r"(r[2]), "=r"(r[3]) : "r"(a));
}

// fp32 K-major tiles for K4 (unchanged path)
#define A_STRIDE 36
// half tile strides (in halfs)
#define AH_STRIDE 40    // 80 bytes: 16B-multiple, conflict-free ldmatrix
#define BH_STRIDE 136   // 272 bytes

// ---- fp16 k-tile (K=32): A [m][k] half stride 40, B raw [k][n] half stride 136 ----
__device__ __forceinline__ void compute_tile_f16(uint32_t ahAddr, uint32_t bwAddr,
                                                 int lane, int wm, int wn, float acc[2][8][4]) {
#pragma unroll
    for (int ks = 0; ks < 2; ks++) {
        const int k0 = ks * 16;
        uint32_t a[2][4];
#pragma unroll
        for (int i = 0; i < 2; i++) {
            int row = wm + i * 16 + (lane & 15);
            int kof = k0 + ((lane >> 4) << 3);
            ldsm_x4(a[i], ahAddr + row * (AH_STRIDE * 2) + kof * 2);
        }
        uint32_t bb[8][2];
#pragma unroll
        for (int j16 = 0; j16 < 4; j16++) {
            int krow = k0 + (lane & 7) + ((lane & 8) ? 8 : 0);
            int ncol = wn + j16 * 16 + ((lane & 16) ? 8 : 0);
            uint32_t rr[4];
            ldsm_x4_t(rr, bwAddr + krow * (BH_STRIDE * 2) + ncol * 2);
            bb[j16 * 2][0] = rr[0]; bb[j16 * 2][1] = rr[1];
            bb[j16 * 2 + 1][0] = rr[2]; bb[j16 * 2 + 1][1] = rr[3];
        }
#pragma unroll
        for (int i = 0; i < 2; i++)
#pragma unroll
            for (int j = 0; j < 8; j++)
                mma_f16(acc[i][j], a[i], bb[j]);
    }
}

// ---- tf32 k-tile for K4: BOTH operands [row][k] fp32 stride-36 ----
__device__ __forceinline__ void compute_tile_kk(const float* As_, const float* Bs_,
                                                int lane, int wm, int wn, float acc[2][8][4]) {
    const int lr = lane >> 2, lc = lane & 3;
#pragma unroll
    for (int ks = 0; ks < 4; ks++) {
        const int k0 = ks * 8;
        uint32_t a[2][4];
#pragma unroll
        for (int i = 0; i < 2; i++) {
            const float* ap = As_ + (size_t)(wm + i * 16 + lr) * A_STRIDE + k0 + lc;
            a[i][0] = __float_as_uint(ap[0]);
            a[i][1] = __float_as_uint(ap[8 * A_STRIDE]);
            a[i][2] = __float_as_uint(ap[4]);
            a[i][3] = __float_as_uint(ap[8 * A_STRIDE + 4]);
        }
        uint32_t bb[8][2];
#pragma unroll
        for (int j = 0; j < 8; j++) {
            const float* bp = Bs_ + (size_t)(wn + j * 8 + lr) * A_STRIDE + k0 + lc;
            bb[j][0] = __float_as_uint(bp[0]);
            bb[j][1] = __float_as_uint(bp[4]);
        }
#pragma unroll
        for (int i = 0; i < 2; i++)
#pragma unroll
            for (int j = 0; j < 8; j++)
                mma_tf32(acc[i][j], a[i], bb[j]);
    }
}

// ---------------- prep: stack weights (half) + bias ----------------
__global__ void k_prep(const float* __restrict__ w_o, const float* __restrict__ b_o,
                       const float* __restrict__ w_v, const float* __restrict__ b_v) {
    int i = blockIdx.x * blockDim.x + threadIdx.x;
    if (i < 128 * 256) {
        g_Wh[i] = __float2half(w_o[i]);
        g_Wh[128 * 256 + i] = __float2half(w_v[i]);
    }
    if (i < 128) {
        g_bias[i] = b_o[i];
        g_bias[128 + i] = b_v[i];
    }
}

// ---------------- convert x -> half ----------------
__global__ void k_xh(const float* __restrict__ x) {
    size_t i = (size_t)blockIdx.x * 256 + threadIdx.x;   // 8 elems each
    const float4* p = (const float4*)x + i * 2;
    float4 u = p[0], v = p[1];
    __half2 h[4];
    h[0] = __floats2half2_rn(u.x, u.y);
    h[1] = __floats2half2_rn(u.z, u.w);
    h[2] = __floats2half2_rn(v.x, v.y);
    h[3] = __floats2half2_rn(v.z, v.w);
    *(uint4*)(g_xh + i * 8) = *(uint4*)h;
}

// ---------------- K1 fp16: [o;v] = W @ x + bias ----------------
// grid (NPIX/128, 2, BATCH), block 256 (8 warps: 4m x 2n)
__global__ __launch_bounds__(256)
void k1_f16() {
    __shared__ __align__(16) __half sAh[2][128 * AH_STRIDE];   // 20480 B
    __shared__ __align__(16) __half sBw[2][32 * BH_STRIDE];    // 17408 B
    const uint32_t ahA = smem_u32(sAh);
    const uint32_t bwA = smem_u32(sBw);

    const int t = threadIdx.x;
    const int lane = t & 31, wid = t >> 5;
    const int wm = (wid & 3) * 32, wn = (wid >> 2) * 64;
    const int b = blockIdx.z;
    const int m0 = blockIdx.y * 128;
    const int col0 = blockIdx.x * 128;
    const __half* Xb = g_xh + (size_t)b * CIN * NPIX;

    float acc[2][8][4];
#pragma unroll
    for (int i = 0; i < 2; i++)
#pragma unroll
        for (int j = 0; j < 8; j++)
#pragma unroll
            for (int r = 0; r < 4; r++) acc[i][j][r] = 0.f;

    // prologue
    {
#pragma unroll
        for (int i = 0; i < 2; i++) {
            int lin = t + i * 256;
            int r = lin >> 2, q = lin & 3;
            CP16(ahA + (uint32_t)(r * AH_STRIDE + q * 8) * 2,
                 g_Wh + (size_t)(m0 + r) * 256 + q * 8);
        }
#pragma unroll
        for (int i = 0; i < 2; i++) {
            int lin = t + i * 256;
            int r = lin >> 4, q = lin & 15;
            CP16(bwA + (uint32_t)(r * BH_STRIDE + q * 8) * 2,
                 Xb + (size_t)r * NPIX + col0 + q * 8);
        }
        CP_COMMIT;
    }

    for (int kt = 0; kt < 8; kt++) {
        const int buf = kt & 1;
        if (kt < 7) {
            const int nbuf = (kt + 1) & 1;
            const int kc = (kt + 1) * 32;
#pragma unroll
            for (int i = 0; i < 2; i++) {
                int lin = t + i * 256;
                int r = lin >> 2, q = lin & 3;
                CP16(ahA + (uint32_t)(nbuf * 128 * AH_STRIDE + r * AH_STRIDE + q * 8) * 2,
                     g_Wh + (size_t)(m0 + r) * 256 + kc + q * 8);
            }
#pragma unroll
            for (int i = 0; i < 2; i++) {
                int lin = t + i * 256;
                int r = lin >> 4, q = lin & 15;
                CP16(bwA + (uint32_t)(nbuf * 32 * BH_STRIDE + r * BH_STRIDE + q * 8) * 2,
                     Xb + (size_t)(kc + r) * NPIX + col0 + q * 8);
            }
            CP_COMMIT;
            CP_WAIT1;
        } else {
            CP_WAIT0;
        }
        __syncthreads();
        compute_tile_f16(ahA + buf * 128 * AH_STRIDE * 2,
                         bwA + buf * 32 * BH_STRIDE * 2, lane, wm, wn, acc);
        __syncthreads();
    }

    const int lr = lane >> 2, lc = lane & 3;
    if (blockIdx.y == 0) {
        // o: write half
        __half* dst = g_oh + (size_t)b * 128 * NPIX;
#pragma unroll
        for (int i = 0; i < 2; i++) {
            int r1 = wm + i * 16 + lr, r2 = r1 + 8;
            float b1 = g_bias[r1], b2 = g_bias[r2];
#pragma unroll
            for (int j = 0; j < 8; j++) {
                int col = col0 + wn + j * 8 + lc * 2;
                __half2 h1 = __floats2half2_rn(acc[i][j][0] + b1, acc[i][j][1] + b1);
                __half2 h2 = __floats2half2_rn(acc[i][j][2] + b2, acc[i][j][3] + b2);
                *(__half2*)(dst + (size_t)r1 * NPIX + col) = h1;
                *(__half2*)(dst + (size_t)r2 * NPIX + col) = h2;
            }
        }
    } else {
        // v: write fp32
        float* dst = g_v + (size_t)b * 128 * NPIX;
#pragma unroll
        for (int i = 0; i < 2; i++) {
            int r1 = wm + i * 16 + lr, r2 = r1 + 8;
            float b1 = g_bias[128 + r1], b2 = g_bias[128 + r2];
#pragma unroll
            for (int j = 0; j < 8; j++) {
                int col = col0 + wn + j * 8 + lc * 2;
                float2 v1 = {acc[i][j][0] + b1, acc[i][j][1] + b1};
                float2 v2 = {acc[i][j][2] + b2, acc[i][j][3] + b2};
                *(float2*)(dst + (size_t)r1 * NPIX + col) = v1;
                *(float2*)(dst + (size_t)r2 * NPIX + col) = v2;
            }
        }
    }
}

// ---------------- stats: h[n]=1/colsum(e^v), rowpart ----------------
__global__ __launch_bounds__(256)
void k_stats() {
    __shared__ float vb[128][68];
    __shared__ float reds[4][64];
    const int nblk = blockIdx.x, b = blockIdx.y;
    const int n0 = nblk * 64;
    const float* vbase = g_v + (size_t)b * 128 * NPIX + n0;
    const int t = threadIdx.x;

#pragma unroll
    for (int i = 0; i < 8; i++) {
        int lin = t + i * 256;
        int r = lin >> 4, q = lin & 15;
        float4 v = *(const float4*)(vbase + (size_t)r * NPIX + q * 4);
        *(float4*)&vb[r][q * 4] = v;
    }
    __syncthreads();

    const int pix = t & 63, quar = t >> 6;
    float s = 0.f;
#pragma unroll 8
    for (int i = 0; i < 32; i++) {
        int m = quar * 32 + i;
        float e = __expf(vb[m][pix]);
        vb[m][pix] = e;
        s += e;
    }
    reds[quar][pix] = s;
    __syncthreads();
    if (quar == 0) {
        float tot = reds[0][pix] + reds[1][pix] + reds[2][pix] + reds[3][pix];
        g_h[(size_t)b * NPIX + n0 + pix] = 1.f / tot;
    }

    const int r = t >> 1, half = t & 1;
    float rs = 0.f;
#pragma unroll 8
    for (int i = 0; i < 32; i++) rs += vb[r][half * 32 + i];
    rs += __shfl_xor_sync(~0u, rs, 1);
    if (half == 0)
        g_rowpart[((size_t)b * MED + r) * 64 + nblk] = rs;
}

// ---------------- alpha: warp per row ----------------
__global__ void k_alpha() {
    const int b = blockIdx.x;
    const int m = blockIdx.y * 32 + (threadIdx.x >> 5);
    const int lane = threadIdx.x & 31;
    float2 v = *(const float2*)(g_rowpart + ((size_t)b * MED + m) * 64 + lane * 2);
    float s = v.x + v.y;
#pragma unroll
    for (int o = 16; o; o >>= 1) s += __shfl_xor_sync(~0u, s, o);
    if (lane == 0) g_alpha[b * MED + m] = 1.f / s;
}

// ---------------- K4: S partials via tf32 mma on exp tiles ----------------
#define K4_RSTRIDE 36
#define K4_RAWF (128 * K4_RSTRIDE)
#define K4_SMEM_F (2 * K4_RAWF + 2 * (128 * A_STRIDE) + 512)
#define K4_SMEM_BYTES (K4_SMEM_F * 4)
__global__ __launch_bounds__(256)
void k4_mma() {
    extern __shared__ float sm4[];
    float* raw = sm4;
    float* E   = sm4 + 2 * K4_RAWF;
    float* EH  = E + 128 * A_STRIDE;
    float* hsh = EH + 128 * A_STRIDE;
    const uint32_t raw_u32 = smem_u32(raw);

    const int t = threadIdx.x;
    const int lane = t & 31, wid = t >> 5;
    const int wm = (wid & 3) * 32, wn = (wid >> 2) * 64;
    const int split = blockIdx.x, b = blockIdx.y;
    const int n0 = split * 512;
    const float* V = g_v + (size_t)b * 128 * NPIX + n0;

    for (int i = t; i < 512; i += 256) hsh[i] = g_h[(size_t)b * NPIX + n0 + i];

    float acc[2][8][4];
#pragma unroll
    for (int i = 0; i < 2; i++)
#pragma unroll
        for (int j = 0; j < 8; j++)
#pragma unroll
            for (int r = 0; r < 4; r++) acc[i][j][r] = 0.f;

#pragma unroll
    for (int i = 0; i < 4; i++) {
        int lin = t + i * 256;
        int r = lin >> 3, q = lin & 7;
        CP16(raw_u32 + (uint32_t)(r * K4_RSTRIDE + q * 4) * 4, V + (size_t)r * NPIX + q * 4);
    }
    CP_COMMIT;

    const int cr = t >> 1, cc0 = (t & 1) * 16;
    for (int s = 0; s < 16; s++) {
        const int buf = s & 1;
        if (s < 15) {
            const int nbuf = (s + 1) & 1;
            const int scol = (s + 1) * 32;
#pragma unroll
            for (int i = 0; i < 4; i++) {
                int lin = t + i * 256;
                int r = lin >> 3, q = lin & 7;
                CP16(raw_u32 + (uint32_t)(nbuf * K4_RAWF + r * K4_RSTRIDE + q * 4) * 4,
                     V + (size_t)r * NPIX + scol + q * 4);
            }
            CP_COMMIT;
            CP_WAIT1;
        } else {
            CP_WAIT0;
        }
        __syncthreads();
        const float* rb = raw + buf * K4_RAWF;
#pragma unroll
        for (int i = 0; i < 16; i++) {
            int c = cc0 + i;
            float e = __expf(rb[cr * K4_RSTRIDE + c]);
            E[cr * A_STRIDE + c] = e;
            EH[cr * A_STRIDE + c] = e * hsh[s * 32 + c];
        }
        __syncthreads();
        compute_tile_kk(EH, E, lane, wm, wn, acc);
    }

    float* out = g_Apart + ((size_t)b * 8 + split) * (MED * MED);
    const int lr = lane >> 2, lc = lane & 3;
#pragma unroll
    for (int i = 0; i < 2; i++) {
        int r1 = wm + i * 16 + lr, r2 = r1 + 8;
#pragma unroll
        for (int j = 0; j < 8; j++) {
            int col = wn + j * 8 + lc * 2;
            *(float2*)(out + (size_t)r1 * MED + col) = make_float2(acc[i][j][0], acc[i][j][1]);
            *(float2*)(out + (size_t)r2 * MED + col) = make_float2(acc[i][j][2], acc[i][j][3]);
        }
    }
}

// ---------------- Wb fused: Wbh[b][c][m] = half(alpha_m * sum_k w_c[c][k]*S[m][k]) ----------------
__global__ __launch_bounds__(256, 2)
void k_gemmWb(const float* __restrict__ w_c) {
    __shared__ float As_[32][136];
    __shared__ float Ws[128][33];
    const int b = blockIdx.x;
    const int ch = blockIdx.y;
    const float* Ap = g_Apart + (size_t)b * 8 * MED * MED;
    const int t = threadIdx.x;
    const int tc = t >> 4, tmn = t & 15;

    float acc[8][8];
#pragma unroll
    for (int i = 0; i < 8; i++)
#pragma unroll
        for (int j = 0; j < 8; j++) acc[i][j] = 0.f;

    for (int k0 = 0; k0 < 128; k0 += 32) {
#pragma unroll
        for (int i = 0; i < 16; i++) {
            int lin = t + i * 256;
            int m = lin >> 5, kk = lin & 31;
            float s = 0.f;
#pragma unroll
            for (int p = 0; p < 8; p++)
                s += Ap[(size_t)p * MED * MED + (size_t)m * 128 + k0 + kk];
            As_[kk][m] = s;
        }
#pragma unroll
        for (int i = 0; i < 16; i++) {
            int lin = t + i * 256;
            int c = lin >> 5, kk = lin & 31;
            Ws[c][kk] = w_c[(size_t)(ch * 128 + c) * 128 + k0 + kk];
        }
        __syncthreads();
#pragma unroll
        for (int k = 0; k < 32; k++) {
            float w[8], a[8];
#pragma unroll
            for (int i = 0; i < 8; i++) w[i] = Ws[tc * 8 + i][k];
#pragma unroll
            for (int j = 0; j < 8; j++) a[j] = As_[k][tmn * 8 + j];
#pragma unroll
            for (int i = 0; i < 8; i++)
#pragma unroll
                for (int j = 0; j < 8; j++) acc[i][j] += w[i] * a[j];
        }
        __syncthreads();
    }

    float alpha[8];
#pragma unroll
    for (int j = 0; j < 8; j++) alpha[j] = g_alpha[b * MED + tmn * 8 + j];

    __half* out = g_Wbh + (size_t)b * 256 * MED + (size_t)ch * 128 * MED;
#pragma unroll
    for (int i = 0; i < 8; i++)
#pragma unroll
        for (int j = 0; j < 8; j++)
            out[(size_t)(tc * 8 + i) * MED + tmn * 8 + j] = __float2half(acc[i][j] * alpha[j]);
}

// ---------------- K6 fp16: result = gamma*relu(Wb @ o + b_c) + x ----------------
// grid (NPIX/128, 2, BATCH), block 256
__global__ __launch_bounds__(256)
void k6_f16(const float* __restrict__ x, const float* __restrict__ b_c,
            const float* __restrict__ gamma, float* __restrict__ outp) {
    __shared__ __align__(16) __half sAh[2][128 * AH_STRIDE];
    __shared__ __align__(16) __half sBw[2][32 * BH_STRIDE];
    const uint32_t ahA = smem_u32(sAh);
    const uint32_t bwA = smem_u32(sBw);

    const int t = threadIdx.x;
    const int lane = t & 31, wid = t >> 5;
    const int wm = (wid & 3) * 32, wn = (wid >> 2) * 64;
    const int b = blockIdx.z;
    const int m0 = blockIdx.y * 128;      // c offset
    const int col0 = blockIdx.x * 128;    // n offset
    const __half* Ab = g_Wbh + (size_t)b * 256 * MED;
    const __half* Ob = g_oh + (size_t)b * 128 * NPIX;

    float acc[2][8][4];
#pragma unroll
    for (int i = 0; i < 2; i++)
#pragma unroll
        for (int j = 0; j < 8; j++)
#pragma unroll
            for (int r = 0; r < 4; r++) acc[i][j][r] = 0.f;

    {
#pragma unroll
        for (int i = 0; i < 2; i++) {
            int lin = t + i * 256;
            int r = lin >> 2, q = lin & 3;
            CP16(ahA + (uint32_t)(r * AH_STRIDE + q * 8) * 2,
                 Ab + (size_t)(m0 + r) * 128 + q * 8);
        }
#pragma unroll
        for (int i = 0; i < 2; i++) {
            int lin = t + i * 256;
            int r = lin >> 4, q = lin & 15;
            CP16(bwA + (uint32_t)(r * BH_STRIDE + q * 8) * 2,
                 Ob + (size_t)r * NPIX + col0 + q * 8);
        }
        CP_COMMIT;
    }

    for (int kt = 0; kt < 4; kt++) {
        const int buf = kt & 1;
        if (kt < 3) {
            const int nbuf = (kt + 1) & 1;
            const int kc = (kt + 1) * 32;
#pragma unroll
            for (int i = 0; i < 2; i++) {
                int lin = t + i * 256;
                int r = lin >> 2, q = lin & 3;
                CP16(ahA + (uint32_t)(nbuf * 128 * AH_STRIDE + r * AH_STRIDE + q * 8) * 2,
                     Ab + (size_t)(m0 + r) * 128 + kc + q * 8);
            }
#pragma unroll
            for (int i = 0; i < 2; i++) {
                int lin = t + i * 256;
                int r = lin >> 4, q = lin & 15;
                CP16(bwA + (uint32_t)(nbuf * 32 * BH_STRIDE + r * BH_STRIDE + q * 8) * 2,
                     Ob + (size_t)(kc + r) * NPIX + col0 + q * 8);
            }
            CP_COMMIT;
            CP_WAIT1;
        } else {
            CP_WAIT0;
        }
        __syncthreads();
        compute_tile_f16(ahA + buf * 128 * AH_STRIDE * 2,
                         bwA + buf * 32 * BH_STRIDE * 2, lane, wm, wn, acc);
        __syncthreads();
    }

    const float g = gamma[0];
    const int lr = lane >> 2, lc = lane & 3;
#pragma unroll
    for (int i = 0; i < 2; i++) {
        int c1 = m0 + wm + i * 16 + lr;
        int c2 = c1 + 8;
        float bc1 = b_c[c1], bc2 = b_c[c2];
#pragma unroll
        for (int j = 0; j < 8; j++) {
            int col = col0 + wn + j * 8 + lc * 2;
            float2 xv1 = *(const float2*)(x + ((size_t)b * CIN + c1) * NPIX + col);
            float2 xv2 = *(const float2*)(x + ((size_t)b * CIN + c2) * NPIX + col);
            float2 o1, o2;
            o1.x = fmaxf(acc[i][j][0] + bc1, 0.f) * g + xv1.x;
            o1.y = fmaxf(acc[i][j][1] + bc1, 0.f) * g + xv1.y;
            o2.x = fmaxf(acc[i][j][2] + bc2, 0.f) * g + xv2.x;
            o2.y = fmaxf(acc[i][j][3] + bc2, 0.f) * g + xv2.y;
            *(float2*)(outp + ((size_t)b * CIN + c1) * NPIX + col) = o1;
            *(float2*)(outp + ((size_t)b * CIN + c2) * NPIX + col) = o2;
        }
    }
}

// ---------------- launch ----------------
extern "C" void kernel_launch(void* const* d_in, const int* in_sizes, int n_in,
                              void* d_out, int out_size) {
    const float* x     = (const float*)d_in[0];
    const float* w_o   = (const float*)d_in[1];
    const float* b_o   = (const float*)d_in[2];
    const float* w_v   = (const float*)d_in[3];
    const float* b_v   = (const float*)d_in[4];
    const float* w_c   = (const float*)d_in[5];
    const float* b_c   = (const float*)d_in[6];
    const float* gamma = (const float*)d_in[7];
    float* out = (float*)d_out;

    cudaFuncSetAttribute(k4_mma, cudaFuncAttributeMaxDynamicSharedMemorySize, K4_SMEM_BYTES);

    k_prep<<<128, 256>>>(w_o, b_o, w_v, b_v);
    k_xh<<<8192, 256>>>(x);
    k1_f16<<<dim3(NPIX / 128, 2, BATCH), 256>>>();
    k_stats<<<dim3(64, BATCH), 256>>>();
    k_alpha<<<dim3(BATCH, 4), 1024>>>();
    k4_mma<<<dim3(8, BATCH), 256, K4_SMEM_BYTES>>>();
    k_gemmWb<<<dim3(BATCH, 2), 256>>>(w_c);
    k6_f16<<<dim3(NPIX / 128, 2, BATCH), 256>>>(x, b_c, gamma, out);
}

// round 7
// speedup vs baseline: 3.3826x; 1.1873x over previous
#include <cuda_runtime.h>
#include <cuda_fp16.h>
#include <cstdint>

#define BATCH 16
#define CIN   256
#define MED   128
#define NPIX  4096

// ---------------- scratch ----------------
__device__ __half g_Wh[256 * 256];                    // stacked [w_o; w_v] half
__device__ float  g_bias[256];
__device__ __half g_oh[(size_t)BATCH * 128 * NPIX];   // o half (K6 operand)
__device__ __half g_vh[(size_t)BATCH * 128 * NPIX];   // v logits half
__device__ float  g_sqh[BATCH * NPIX];                // sqrt(1 / col-sum of e^v)
__device__ float  g_rowpart[BATCH * MED * 64];        // partial row sums of e^v
__device__ float  g_alpha[BATCH * MED];               // 1 / row-sum of e^v
__device__ float  g_Apart[BATCH * 8 * MED * MED];     // split-K partials of S
__device__ __half g_Wbh[BATCH * 256 * MED];           // Wb half [b][c][m]

// ======================= helpers =======================
__device__ __forceinline__ uint32_t smem_u32(const void* p) {
    uint32_t a;
    asm("{ .reg .u64 t; cvta.to.shared.u64 t, %1; cvt.u32.u64 %0, t; }" : "=r"(a) : "l"(p));
    return a;
}

#define CP16(dst, src) \
    asm volatile("cp.async.ca.shared.global [%0], [%1], 16;" :: "r"(dst), "l"(src) : "memory")
#define CP_COMMIT asm volatile("cp.async.commit_group;" ::: "memory")
#define CP_WAIT1  asm volatile("cp.async.wait_group 1;" ::: "memory")
#define CP_WAIT0  asm volatile("cp.async.wait_group 0;" ::: "memory")

__device__ __forceinline__ void mma_f16(float* d, const uint32_t* a, const uint32_t* b) {
    asm volatile(
        "mma.sync.aligned.m16n8k16.row.col.f32.f16.f16.f32 "
        "{%0,%1,%2,%3}, {%4,%5,%6,%7}, {%8,%9}, {%0,%1,%2,%3};"
        : "+f"(d[0]), "+f"(d[1]), "+f"(d[2]), "+f"(d[3])
        : "r"(a[0]), "r"(a[1]), "r"(a[2]), "r"(a[3]), "r"(b[0]), "r"(b[1]));
}

__device__ __forceinline__ void ldsm_x4(uint32_t* r, uint32_t a) {
    asm volatile("ldmatrix.sync.aligned.m8n8.x4.shared.b16 {%0,%1,%2,%3}, [%4];"
                 : "=r"(r[0]), "=r"(r[1]), "=r"(r[2]), "=r"(r[3]) : "r"(a));
}
__device__ __forceinline__ void ldsm_x4_t(uint32_t* r, uint32_t a) {
    asm volatile("ldmatrix.sync.aligned.m8n8.x4.trans.shared.b16 {%0,%1,%2,%3}, [%4];"
                 : "=r"(r[0]), "=r"(r[1]), "=r"(r[2]), "=r"(r[3]) : "r"(a));
}

#define AH_STRIDE 40    // halfs; 80B rows, conflict-free ldmatrix
#define BH_STRIDE 136   // halfs; 272B rows

// ---- fp16 k-tile (K=32): A [m][k] stride 40, B raw [k][n] stride 136 ----
__device__ __forceinline__ void compute_tile_f16(uint32_t ahAddr, uint32_t bwAddr,
                                                 int lane, int wm, int wn, float acc[2][8][4]) {
#pragma unroll
    for (int ks = 0; ks < 2; ks++) {
        const int k0 = ks * 16;
        uint32_t a[2][4];
#pragma unroll
        for (int i = 0; i < 2; i++) {
            int row = wm + i * 16 + (lane & 15);
            int kof = k0 + ((lane >> 4) << 3);
            ldsm_x4(a[i], ahAddr + row * (AH_STRIDE * 2) + kof * 2);
        }
        uint32_t bb[8][2];
#pragma unroll
        for (int j16 = 0; j16 < 4; j16++) {
            int krow = k0 + (lane & 7) + ((lane & 8) ? 8 : 0);
            int ncol = wn + j16 * 16 + ((lane & 16) ? 8 : 0);
            uint32_t rr[4];
            ldsm_x4_t(rr, bwAddr + krow * (BH_STRIDE * 2) + ncol * 2);
            bb[j16 * 2][0] = rr[0]; bb[j16 * 2][1] = rr[1];
            bb[j16 * 2 + 1][0] = rr[2]; bb[j16 * 2 + 1][1] = rr[3];
        }
#pragma unroll
        for (int i = 0; i < 2; i++)
#pragma unroll
            for (int j = 0; j < 8; j++)
                mma_f16(acc[i][j], a[i], bb[j]);
    }
}

// ---- fp16 symmetric k-tile (K=32): BOTH operands from F [row][k] stride 40 ----
__device__ __forceinline__ void compute_tile_sym(uint32_t fAddr,
                                                 int lane, int wm, int wn, float acc[2][8][4]) {
#pragma unroll
    for (int ks = 0; ks < 2; ks++) {
        const int k0 = ks * 16;
        uint32_t a[2][4];
#pragma unroll
        for (int i = 0; i < 2; i++) {
            int row = wm + i * 16 + (lane & 15);
            int kof = k0 + ((lane >> 4) << 3);
            ldsm_x4(a[i], fAddr + row * (AH_STRIDE * 2) + kof * 2);
        }
        uint32_t bb[8][2];
#pragma unroll
        for (int j16 = 0; j16 < 4; j16++) {
            int mat = lane >> 3;
            int row = wn + j16 * 16 + (mat & 1) * 8 + (lane & 7);
            int kof = k0 + (mat >> 1) * 8;
            uint32_t rr[4];
            ldsm_x4(rr, fAddr + row * (AH_STRIDE * 2) + kof * 2);
            bb[j16 * 2][0] = rr[0]; bb[j16 * 2][1] = rr[2];
            bb[j16 * 2 + 1][0] = rr[1]; bb[j16 * 2 + 1][1] = rr[3];
        }
#pragma unroll
        for (int i = 0; i < 2; i++)
#pragma unroll
            for (int j = 0; j < 8; j++)
                mma_f16(acc[i][j], a[i], bb[j]);
    }
}

// ---------------- prep: stack weights (half) + bias ----------------
__global__ void k_prep(const float* __restrict__ w_o, const float* __restrict__ b_o,
                       const float* __restrict__ w_v, const float* __restrict__ b_v) {
    int i = blockIdx.x * blockDim.x + threadIdx.x;
    if (i < 128 * 256) {
        g_Wh[i] = __float2half(w_o[i]);
        g_Wh[128 * 256 + i] = __float2half(w_v[i]);
    }
    if (i < 128) {
        g_bias[i] = b_o[i];
        g_bias[128 + i] = b_v[i];
    }
}

// ---------------- K1 fp16: [o;v] = W @ x + bias (reads fp32 x, converts inline) ----------------
// grid (NPIX/128, 2, BATCH), block 256 (8 warps: 4m x 2n)
__global__ __launch_bounds__(256)
void k1_f16(const float* __restrict__ x) {
    __shared__ __align__(16) __half sAh[2][128 * AH_STRIDE];
    __shared__ __align__(16) __half sBw[2][32 * BH_STRIDE];
    const uint32_t ahA = smem_u32(sAh);
    const uint32_t bwA = smem_u32(sBw);

    const int t = threadIdx.x;
    const int lane = t & 31, wid = t >> 5;
    const int wm = (wid & 3) * 32, wn = (wid >> 2) * 64;
    const int b = blockIdx.z;
    const int m0 = blockIdx.y * 128;
    const int col0 = blockIdx.x * 128;
    const float* Xb = x + (size_t)b * CIN * NPIX;

    float acc[2][8][4];
#pragma unroll
    for (int i = 0; i < 2; i++)
#pragma unroll
        for (int j = 0; j < 8; j++)
#pragma unroll
            for (int r = 0; r < 4; r++) acc[i][j][r] = 0.f;

    // B stage registers: thread covers rows wid + i*8, float4 col = lane
    float4 xr[4];
    // prologue
#pragma unroll
    for (int i = 0; i < 4; i++)
        xr[i] = *(const float4*)(Xb + (size_t)(wid + i * 8) * NPIX + col0 + lane * 4);
#pragma unroll
    for (int i = 0; i < 2; i++) {
        int lin = t + i * 256;
        int r = lin >> 2, q = lin & 3;
        CP16(ahA + (uint32_t)(r * AH_STRIDE + q * 8) * 2,
             g_Wh + (size_t)(m0 + r) * 256 + q * 8);
    }
    CP_COMMIT;

    for (int kt = 0; kt < 8; kt++) {
        const int buf = kt & 1;
        // convert staged B regs -> half smem [k][n] layout
#pragma unroll
        for (int i = 0; i < 4; i++) {
            int r = wid + i * 8;
            __half2 h0 = __floats2half2_rn(xr[i].x, xr[i].y);
            __half2 h1 = __floats2half2_rn(xr[i].z, xr[i].w);
            uint2 pk = {*(uint32_t*)&h0, *(uint32_t*)&h1};
            *(uint2*)((char*)sBw + ((size_t)buf * 32 * BH_STRIDE + r * BH_STRIDE + lane * 4) * 2) = pk;
        }
        if (kt < 7) {
            const int nbuf = (kt + 1) & 1;
            const int kc = (kt + 1) * 32;
#pragma unroll
            for (int i = 0; i < 4; i++)
                xr[i] = *(const float4*)(Xb + (size_t)(kc + wid + i * 8) * NPIX + col0 + lane * 4);
#pragma unroll
            for (int i = 0; i < 2; i++) {
                int lin = t + i * 256;
                int r = lin >> 2, q = lin & 3;
                CP16(ahA + (uint32_t)(nbuf * 128 * AH_STRIDE + r * AH_STRIDE + q * 8) * 2,
                     g_Wh + (size_t)(m0 + r) * 256 + kc + q * 8);
            }
            CP_COMMIT;
            CP_WAIT1;
        } else {
            CP_WAIT0;
        }
        __syncthreads();
        compute_tile_f16(ahA + buf * 128 * AH_STRIDE * 2,
                         bwA + buf * 32 * BH_STRIDE * 2, lane, wm, wn, acc);
        __syncthreads();
    }

    const int lr = lane >> 2, lc = lane & 3;
    __half* dst = (blockIdx.y == 0 ? g_oh : g_vh) + (size_t)b * 128 * NPIX;
    const int boff = blockIdx.y * 128;
#pragma unroll
    for (int i = 0; i < 2; i++) {
        int r1 = wm + i * 16 + lr, r2 = r1 + 8;
        float b1 = g_bias[boff + r1], b2 = g_bias[boff + r2];
#pragma unroll
        for (int j = 0; j < 8; j++) {
            int col = col0 + wn + j * 8 + lc * 2;
            __half2 h1 = __floats2half2_rn(acc[i][j][0] + b1, acc[i][j][1] + b1);
            __half2 h2 = __floats2half2_rn(acc[i][j][2] + b2, acc[i][j][3] + b2);
            *(__half2*)(dst + (size_t)r1 * NPIX + col) = h1;
            *(__half2*)(dst + (size_t)r2 * NPIX + col) = h2;
        }
    }
}

// ---------------- stats: sqh[n]=rsqrt(colsum e^v), rowpart ----------------
// grid (64, 16), block 256; v tile 128x64 (half in, float smem)
__global__ __launch_bounds__(256)
void k_stats() {
    __shared__ float vb[128][68];
    __shared__ float reds[4][64];
    const int nblk = blockIdx.x, b = blockIdx.y;
    const int n0 = nblk * 64;
    const __half* vbase = g_vh + (size_t)b * 128 * NPIX + n0;
    const int t = threadIdx.x;

#pragma unroll
    for (int i = 0; i < 16; i++) {
        int lin = t + i * 256;                  // 4096 half2 slots
        int r = lin >> 5, q = lin & 31;
        __half2 h = *(const __half2*)(vbase + (size_t)r * NPIX + q * 2);
        float2 f = __half22float2(h);
        vb[r][q * 2] = f.x;
        vb[r][q * 2 + 1] = f.y;
    }
    __syncthreads();

    const int pix = t & 63, quar = t >> 6;
    float s = 0.f;
#pragma unroll 8
    for (int i = 0; i < 32; i++) {
        int m = quar * 32 + i;
        float e = __expf(vb[m][pix]);
        vb[m][pix] = e;
        s += e;
    }
    reds[quar][pix] = s;
    __syncthreads();
    if (quar == 0) {
        float tot = reds[0][pix] + reds[1][pix] + reds[2][pix] + reds[3][pix];
        g_sqh[(size_t)b * NPIX + n0 + pix] = rsqrtf(tot);
    }

    const int r = t >> 1, half = t & 1;
    float rs = 0.f;
#pragma unroll 8
    for (int i = 0; i < 32; i++) rs += vb[r][half * 32 + i];
    rs += __shfl_xor_sync(~0u, rs, 1);
    if (half == 0)
        g_rowpart[((size_t)b * MED + r) * 64 + nblk] = rs;
}

// ---------------- alpha: warp per row ----------------
__global__ void k_alpha() {
    const int b = blockIdx.x;
    const int m = blockIdx.y * 32 + (threadIdx.x >> 5);
    const int lane = threadIdx.x & 31;
    float2 v = *(const float2*)(g_rowpart + ((size_t)b * MED + m) * 64 + lane * 2);
    float s = v.x + v.y;
#pragma unroll
    for (int o = 16; o; o >>= 1) s += __shfl_xor_sync(~0u, s, o);
    if (lane == 0) g_alpha[b * MED + m] = 1.f / s;
}

// ---------------- K4: S = F F^T, F = e^v * sqrt(h), fp16 symmetric mma ----------------
// grid (8 splits, 16 b), block 256. 128x128 output, 512-long contraction over n.
__global__ __launch_bounds__(256)
void k4_mma() {
    __shared__ __align__(16) __half raw[2][128 * AH_STRIDE];   // 20 KB
    __shared__ __align__(16) __half F[128 * AH_STRIDE];        // 10 KB
    __shared__ float sqh[512];
    const uint32_t raw_u32 = smem_u32(raw);
    const uint32_t f_u32 = smem_u32(F);

    const int t = threadIdx.x;
    const int lane = t & 31, wid = t >> 5;
    const int wm = (wid & 3) * 32, wn = (wid >> 2) * 64;
    const int split = blockIdx.x, b = blockIdx.y;
    const int n0 = split * 512;
    const __half* V = g_vh + (size_t)b * 128 * NPIX + n0;

    for (int i = t; i < 512; i += 256) sqh[i] = g_sqh[(size_t)b * NPIX + n0 + i];

    float acc[2][8][4];
#pragma unroll
    for (int i = 0; i < 2; i++)
#pragma unroll
        for (int j = 0; j < 8; j++)
#pragma unroll
            for (int r = 0; r < 4; r++) acc[i][j][r] = 0.f;

    // prologue: raw[0] <- v[:, 0:32] (32 halfs = 64 B per row, 2 cp16 per thread)
#pragma unroll
    for (int i = 0; i < 2; i++) {
        int lin = t + i * 256;            // 512 slots: r*4 + qq
        int r = lin >> 2, qq = lin & 3;
        CP16(raw_u32 + (uint32_t)(r * AH_STRIDE + qq * 8) * 2, V + (size_t)r * NPIX + qq * 8);
    }
    CP_COMMIT;

    const int cr = t >> 1, cc0 = (t & 1) * 16;
    for (int s = 0; s < 16; s++) {
        const int buf = s & 1;
        if (s < 15) {
            const int nbuf = (s + 1) & 1;
            const int scol = (s + 1) * 32;
#pragma unroll
            for (int i = 0; i < 2; i++) {
                int lin = t + i * 256;
                int r = lin >> 2, qq = lin & 3;
                CP16(raw_u32 + (uint32_t)(nbuf * 128 * AH_STRIDE + r * AH_STRIDE + qq * 8) * 2,
                     V + (size_t)r * NPIX + scol + qq * 8);
            }
            CP_COMMIT;
            CP_WAIT1;
        } else {
            CP_WAIT0;
        }
        __syncthreads();   // raw[buf] ready AND previous compute done reading F
        const __half* rb = raw[buf];
#pragma unroll
        for (int i = 0; i < 16; i++) {
            int c = cc0 + i;
            float e = __expf(__half2float(rb[cr * AH_STRIDE + c])) * sqh[s * 32 + c];
            F[cr * AH_STRIDE + c] = __float2half(e);
        }
        __syncthreads();
        compute_tile_sym(f_u32, lane, wm, wn, acc);
    }

    float* out = g_Apart + ((size_t)b * 8 + split) * (MED * MED);
    const int lr = lane >> 2, lc = lane & 3;
#pragma unroll
    for (int i = 0; i < 2; i++) {
        int r1 = wm + i * 16 + lr, r2 = r1 + 8;
#pragma unroll
        for (int j = 0; j < 8; j++) {
            int col = wn + j * 8 + lc * 2;
            *(float2*)(out + (size_t)r1 * MED + col) = make_float2(acc[i][j][0], acc[i][j][1]);
            *(float2*)(out + (size_t)r2 * MED + col) = make_float2(acc[i][j][2], acc[i][j][3]);
        }
    }
}

// ---------------- Wb fused: Wbh[b][c][m] = half(alpha_m * sum_k w_c[c][k]*S[m][k]) ----------------
__global__ __launch_bounds__(256, 2)
void k_gemmWb(const float* __restrict__ w_c) {
    __shared__ float As_[32][136];
    __shared__ float Ws[128][33];
    const int b = blockIdx.x;
    const int ch = blockIdx.y;
    const float* Ap = g_Apart + (size_t)b * 8 * MED * MED;
    const int t = threadIdx.x;
    const int tc = t >> 4, tmn = t & 15;

    float acc[8][8];
#pragma unroll
    for (int i = 0; i < 8; i++)
#pragma unroll
        for (int j = 0; j < 8; j++) acc[i][j] = 0.f;

    for (int k0 = 0; k0 < 128; k0 += 32) {
#pragma unroll
        for (int i = 0; i < 16; i++) {
            int lin = t + i * 256;
            int m = lin >> 5, kk = lin & 31;
            float s = 0.f;
#pragma unroll
            for (int p = 0; p < 8; p++)
                s += Ap[(size_t)p * MED * MED + (size_t)m * 128 + k0 + kk];
            As_[kk][m] = s;
        }
#pragma unroll
        for (int i = 0; i < 16; i++) {
            int lin = t + i * 256;
            int c = lin >> 5, kk = lin & 31;
            Ws[c][kk] = w_c[(size_t)(ch * 128 + c) * 128 + k0 + kk];
        }
        __syncthreads();
#pragma unroll
        for (int k = 0; k < 32; k++) {
            float w[8], a[8];
#pragma unroll
            for (int i = 0; i < 8; i++) w[i] = Ws[tc * 8 + i][k];
#pragma unroll
            for (int j = 0; j < 8; j++) a[j] = As_[k][tmn * 8 + j];
#pragma unroll
            for (int i = 0; i < 8; i++)
#pragma unroll
                for (int j = 0; j < 8; j++) acc[i][j] += w[i] * a[j];
        }
        __syncthreads();
    }

    float alpha[8];
#pragma unroll
    for (int j = 0; j < 8; j++) alpha[j] = g_alpha[b * MED + tmn * 8 + j];

    __half* out = g_Wbh + (size_t)b * 256 * MED + (size_t)ch * 128 * MED;
#pragma unroll
    for (int i = 0; i < 8; i++)
#pragma unroll
        for (int j = 0; j < 8; j++)
            out[(size_t)(tc * 8 + i) * MED + tmn * 8 + j] = __float2half(acc[i][j] * alpha[j]);
}

// ---------------- K6 fp16: result = gamma*relu(Wb @ o + b_c) + x ----------------
__global__ __launch_bounds__(256)
void k6_f16(const float* __restrict__ x, const float* __restrict__ b_c,
            const float* __restrict__ gamma, float* __restrict__ outp) {
    __shared__ __align__(16) __half sAh[2][128 * AH_STRIDE];
    __shared__ __align__(16) __half sBw[2][32 * BH_STRIDE];
    const uint32_t ahA = smem_u32(sAh);
    const uint32_t bwA = smem_u32(sBw);

    const int t = threadIdx.x;
    const int lane = t & 31, wid = t >> 5;
    const int wm = (wid & 3) * 32, wn = (wid >> 2) * 64;
    const int b = blockIdx.z;
    const int m0 = blockIdx.y * 128;
    const int col0 = blockIdx.x * 128;
    const __half* Ab = g_Wbh + (size_t)b * 256 * MED;
    const __half* Ob = g_oh + (size_t)b * 128 * NPIX;

    float acc[2][8][4];
#pragma unroll
    for (int i = 0; i < 2; i++)
#pragma unroll
        for (int j = 0; j < 8; j++)
#pragma unroll
            for (int r = 0; r < 4; r++) acc[i][j][r] = 0.f;

    {
#pragma unroll
        for (int i = 0; i < 2; i++) {
            int lin = t + i * 256;
            int r = lin >> 2, q = lin & 3;
            CP16(ahA + (uint32_t)(r * AH_STRIDE + q * 8) * 2,
                 Ab + (size_t)(m0 + r) * 128 + q * 8);
        }
#pragma unroll
        for (int i = 0; i < 2; i++) {
            int lin = t + i * 256;
            int r = lin >> 4, q = lin & 15;
            CP16(bwA + (uint32_t)(r * BH_STRIDE + q * 8) * 2,
                 Ob + (size_t)r * NPIX + col0 + q * 8);
        }
        CP_COMMIT;
    }

    for (int kt = 0; kt < 4; kt++) {
        const int buf = kt & 1;
        if (kt < 3) {
            const int nbuf = (kt + 1) & 1;
            const int kc = (kt + 1) * 32;
#pragma unroll
            for (int i = 0; i < 2; i++) {
                int lin = t + i * 256;
                int r = lin >> 2, q = lin & 3;
                CP16(ahA + (uint32_t)(nbuf * 128 * AH_STRIDE + r * AH_STRIDE + q * 8) * 2,
                     Ab + (size_t)(m0 + r) * 128 + kc + q * 8);
            }
#pragma unroll
            for (int i = 0; i < 2; i++) {
                int lin = t + i * 256;
                int r = lin >> 4, q = lin & 15;
                CP16(bwA + (uint32_t)(nbuf * 32 * BH_STRIDE + r * BH_STRIDE + q * 8) * 2,
                     Ob + (size_t)(kc + r) * NPIX + col0 + q * 8);
            }
            CP_COMMIT;
            CP_WAIT1;
        } else {
            CP_WAIT0;
        }
        __syncthreads();
        compute_tile_f16(ahA + buf * 128 * AH_STRIDE * 2,
                         bwA + buf * 32 * BH_STRIDE * 2, lane, wm, wn, acc);
        __syncthreads();
    }

    const float g = gamma[0];
    const int lr = lane >> 2, lc = lane & 3;
#pragma unroll
    for (int i = 0; i < 2; i++) {
        int c1 = m0 + wm + i * 16 + lr;
        int c2 = c1 + 8;
        float bc1 = b_c[c1], bc2 = b_c[c2];
#pragma unroll
        for (int j = 0; j < 8; j++) {
            int col = col0 + wn + j * 8 + lc * 2;
            float2 xv1 = *(const float2*)(x + ((size_t)b * CIN + c1) * NPIX + col);
            float2 xv2 = *(const float2*)(x + ((size_t)b * CIN + c2) * NPIX + col);
            float2 o1, o2;
            o1.x = fmaxf(acc[i][j][0] + bc1, 0.f) * g + xv1.x;
            o1.y = fmaxf(acc[i][j][1] + bc1, 0.f) * g + xv1.y;
            o2.x = fmaxf(acc[i][j][2] + bc2, 0.f) * g + xv2.x;
            o2.y = fmaxf(acc[i][j][3] + bc2, 0.f) * g + xv2.y;
            *(float2*)(outp + ((size_t)b * CIN + c1) * NPIX + col) = o1;
            *(float2*)(outp + ((size_t)b * CIN + c2) * NPIX + col) = o2;
        }
    }
}

// ---------------- launch ----------------
extern "C" void kernel_launch(void* const* d_in, const int* in_sizes, int n_in,
                              void* d_out, int out_size) {
    const float* x     = (const float*)d_in[0];
    const float* w_o   = (const float*)d_in[1];
    const float* b_o   = (const float*)d_in[2];
    const float* w_v   = (const float*)d_in[3];
    const float* b_v   = (const float*)d_in[4];
    const float* w_c   = (const float*)d_in[5];
    const float* b_c   = (const float*)d_in[6];
    const float* gamma = (const float*)d_in[7];
    float* out = (float*)d_out;

    k_prep<<<128, 256>>>(w_o, b_o, w_v, b_v);
    k1_f16<<<dim3(NPIX / 128, 2, BATCH), 256>>>(x);
    k_stats<<<dim3(64, BATCH), 256>>>();
    k_alpha<<<dim3(BATCH, 4), 1024>>>();
    k4_mma<<<dim3(8, BATCH), 256>>>();
    k_gemmWb<<<dim3(BATCH, 2), 256>>>(w_c);
    k6_f16<<<dim3(NPIX / 128, 2, BATCH), 256>>>(x, b_c, gamma, out);
}